// round 12
// baseline (speedup 1.0000x reference)
#include <cuda_runtime.h>
#include <cuda_bf16.h>
#include <math.h>

// Problem constants
#define CB 8
#define CN 1024
#define CD 512
#define CO 512
#define CH 8
#define CHD 64
#define QKVLD 1536   // 3*O
#define MROWS (CB*CN) // 8192

// ---------------- scratch (static device allocations; no cudaMalloc) ----------
__device__ float g_fmask[MROWS];
__device__ __nv_bfloat16 g_xh[MROWS*CD],  g_xl[MROWS*CD];
__device__ __nv_bfloat16 g_qwh[QKVLD*CD], g_qwl[QKVLD*CD];
__device__ __nv_bfloat16 g_w1h[CO*CO], g_w1l[CO*CO];
__device__ __nv_bfloat16 g_w2h[CO*CO], g_w2l[CO*CO];
__device__ __nv_bfloat16 g_wrh[CO*CD], g_wrl[CO*CD];
__device__ __nv_bfloat16 g_qh[(size_t)MROWS*QKVLD], g_ql[(size_t)MROWS*QKVLD];
__device__ __nv_bfloat16 g_Hh[MROWS*CO], g_Hl[MROWS*CO];
__device__ __nv_bfloat16 g_Th[MROWS*CO], g_Tl[MROWS*CO];

// ---------------------------------------------------------------------------
__device__ __forceinline__ void bsplit(float v, __nv_bfloat16& h, __nv_bfloat16& l){
    h = __float2bfloat16(v);
    l = __float2bfloat16(v - __bfloat162float(h));
}
// Packed split: hi = bf16x2(v0,v1), lo = bf16x2 residuals (RN, bit-identical).
__device__ __forceinline__ unsigned pksplit(float v0, float v1, unsigned& lo){
    unsigned hi;
    asm("cvt.rn.bf16x2.f32 %0, %1, %2;" : "=r"(hi) : "f"(v1), "f"(v0));
    float h0 = __uint_as_float(hi << 16);
    float h1 = __uint_as_float(hi & 0xffff0000u);
    asm("cvt.rn.bf16x2.f32 %0, %1, %2;" : "=r"(lo) : "f"(v1 - h1), "f"(v0 - h0));
    return hi;
}
__device__ __forceinline__ void mma16816(float* c, const unsigned* a, const unsigned* b){
    asm volatile("mma.sync.aligned.m16n8k16.row.col.f32.bf16.bf16.f32 "
        "{%0,%1,%2,%3}, {%4,%5,%6,%7}, {%8,%9}, {%0,%1,%2,%3};"
        : "+f"(c[0]), "+f"(c[1]), "+f"(c[2]), "+f"(c[3])
        : "r"(a[0]), "r"(a[1]), "r"(a[2]), "r"(a[3]), "r"(b[0]), "r"(b[1]));
}
__device__ __forceinline__ void ldsm4(unsigned* r, const void* p){
    unsigned a = (unsigned)__cvta_generic_to_shared(p);
    asm volatile("ldmatrix.sync.aligned.m8n8.x4.shared.b16 {%0,%1,%2,%3}, [%4];"
        : "=r"(r[0]), "=r"(r[1]), "=r"(r[2]), "=r"(r[3]) : "r"(a));
}
__device__ __forceinline__ void ldsm4t(unsigned* r, const void* p){
    unsigned a = (unsigned)__cvta_generic_to_shared(p);
    asm volatile("ldmatrix.sync.aligned.m8n8.x4.trans.shared.b16 {%0,%1,%2,%3}, [%4];"
        : "=r"(r[0]), "=r"(r[1]), "=r"(r[2]), "=r"(r[3]) : "r"(a));
}
__device__ __forceinline__ void ldsm2(unsigned* r, const void* p){
    unsigned a = (unsigned)__cvta_generic_to_shared(p);
    asm volatile("ldmatrix.sync.aligned.m8n8.x2.shared.b16 {%0,%1}, [%2];"
        : "=r"(r[0]), "=r"(r[1]) : "r"(a));
}
__device__ __forceinline__ void cpa16(void* dst_smem, const void* src){
    unsigned sa = (unsigned)__cvta_generic_to_shared(dst_smem);
    asm volatile("cp.async.cg.shared.global [%0], [%1], 16;" :: "r"(sa), "l"(src));
}
#define CPA_COMMIT asm volatile("cp.async.commit_group;")
#define CPA_WAIT0  asm volatile("cp.async.wait_group 0;")
// half-CTA named barrier (128 threads)
__device__ __forceinline__ void hbar(int id){
    asm volatile("bar.sync %0, 128;" :: "r"(id) : "memory");
}

// ---------------------------------------------------------------------------
// Mask conversion (dtype auto-detect; bench data treated strictly as data)
// ---------------------------------------------------------------------------
__global__ void mask_convert(const unsigned char* __restrict__ raw,
                             float* __restrict__ fmask)
{
    __shared__ int s_m1, s_m23, s_gt1;
    int t = threadIdx.x;
    if (t == 0) { s_m1 = 0; s_m23 = 0; s_gt1 = 0; }
    __syncthreads();
    int m1 = 0, m23 = 0, g = 0;
    for (int i = t; i < MROWS; i += 256) {
        unsigned char v = raw[i];
        if (v) {
            int p = i & 3;
            if (p == 1) m1 = 1;
            if (p >= 2) m23 = 1;
            if (v > 1) g = 1;
        }
    }
    if (m1)  atomicOr(&s_m1, 1);
    if (m23) atomicOr(&s_m23, 1);
    if (g)   atomicOr(&s_gt1, 1);
    __syncthreads();
    int mis = s_m1 | s_m23;
    int mode;
    if (!mis)            mode = 0;
    else if (!s_gt1)     mode = 1;
    else if (s_m1)       mode = 3;
    else                 mode = 2;
    for (int i = t; i < MROWS; i += 256) {
        float f;
        if (mode == 0)      f = (((const int*)raw)[i]            != 0)   ? 1.f : 0.f;
        else if (mode == 1) f = (raw[i]                          != 0)   ? 1.f : 0.f;
        else if (mode == 2) f = (((const float*)raw)[i]          != 0.f) ? 1.f : 0.f;
        else                f = (((const unsigned short*)raw)[i] != 0)   ? 1.f : 0.f;
        fmask[i] = f;
    }
}

// ---------------------------------------------------------------------------
// Fused splitter: x, qkv_w, w1, w2, wr in one launch.
// ---------------------------------------------------------------------------
#define SPL0 (MROWS*CD)
#define SPL1 (QKVLD*CD)
#define SPL2 (CO*CO)
#define SPL3 (CO*CO)
#define SPL4 (CO*CD)
#define SPLT (SPL0+SPL1+SPL2+SPL3+SPL4)
__global__ void split5(
    const float* __restrict__ s0, const float* __restrict__ s1,
    const float* __restrict__ s2, const float* __restrict__ s3,
    const float* __restrict__ s4,
    __nv_bfloat16* __restrict__ h0, __nv_bfloat16* __restrict__ l0,
    __nv_bfloat16* __restrict__ h1, __nv_bfloat16* __restrict__ l1,
    __nv_bfloat16* __restrict__ h2, __nv_bfloat16* __restrict__ l2,
    __nv_bfloat16* __restrict__ h3, __nv_bfloat16* __restrict__ l3,
    __nv_bfloat16* __restrict__ h4, __nv_bfloat16* __restrict__ l4)
{
    int i = blockIdx.x * 256 + threadIdx.x;
    if (i >= SPLT) return;
    const float* s; __nv_bfloat16 *h, *l; int j = i;
    if (j < SPL0)                { s = s0; h = h0; l = l0; }
    else if ((j -= SPL0) < SPL1) { s = s1; h = h1; l = l1; }
    else if ((j -= SPL1) < SPL2) { s = s2; h = h2; l = l2; }
    else if ((j -= SPL2) < SPL3) { s = s3; h = h3; l = l3; }
    else { j -= SPL3;              s = s4; h = h4; l = l4; }
    __nv_bfloat16 hh, ll;
    bsplit(s[j], hh, ll);
    h[j] = hh; l[j] = ll;
}

// ---------------------------------------------------------------------------
// Tensor-core NT GEMM body (bf16x3), cp.async double-buffered, ldmatrix.
// Dynamic smem: Ah[2][1536] | Al | Wh | Wl = 49152 B. 128x128, BK=16, 256 thr.
// EPI: 0 split-store; 1 relu+split-store; 2 Cf=0.5v; 3 Cf+=0.5*fmask[m]*v
// ---------------------------------------------------------------------------
template<int EPI>
__device__ __forceinline__ void gemm_body(
    unsigned* sm, int bx, int by,
    const __nv_bfloat16* __restrict__ Ahg, const __nv_bfloat16* __restrict__ Alg,
    const __nv_bfloat16* __restrict__ Whg, const __nv_bfloat16* __restrict__ Wlg,
    const float* __restrict__ bias, const float* __restrict__ fmask,
    float* __restrict__ Cf, __nv_bfloat16* __restrict__ Ch, __nv_bfloat16* __restrict__ Cl,
    int K, int lda, int ldw, int ldc)
{
    unsigned* Ah = sm;
    unsigned* Al = sm + 3072;
    unsigned* Wh = sm + 6144;
    unsigned* Wl = sm + 9216;
    const int tid = threadIdx.x;
    const int lane = tid & 31, wid = tid >> 5;
    const int wm = wid & 1, wn = wid >> 1;
    const int row0 = by * 128, col0 = bx * 128;
    const int lr = tid >> 1, lh = tid & 1;
    const int qr = lane >> 2, qk = lane & 3;

    const int arow  = wm*64 + (lane & 7) + ((lane >> 3) & 1) * 8;
    const int aword = ((lane >> 4) & 1) * 4;
    const int brow  = wn*32 + (lane & 7);
    const int bword = ((lane >> 3) & 1) * 4;

    float acc[4][4][4];
    #pragma unroll
    for (int mt = 0; mt < 4; mt++)
        #pragma unroll
        for (int nt = 0; nt < 4; nt++)
            #pragma unroll
            for (int i = 0; i < 4; i++) acc[mt][nt][i] = 0.f;

    {
        size_t aoff = (size_t)(row0 + lr) * lda + lh * 8;
        size_t woff = (size_t)(col0 + lr) * ldw + lh * 8;
        cpa16(&Ah[lr*12 + lh*4], Ahg + aoff);
        cpa16(&Al[lr*12 + lh*4], Alg + aoff);
        cpa16(&Wh[lr*12 + lh*4], Whg + woff);
        cpa16(&Wl[lr*12 + lh*4], Wlg + woff);
    }
    CPA_COMMIT;

    int st = 0;
    for (int k0 = 0; k0 < K; k0 += 16, st ^= 1) {
        CPA_WAIT0;
        __syncthreads();
        if (k0 + 16 < K) {
            int so = (st^1) * 1536;
            size_t aoff = (size_t)(row0 + lr) * lda + k0 + 16 + lh * 8;
            size_t woff = (size_t)(col0 + lr) * ldw + k0 + 16 + lh * 8;
            cpa16(&Ah[so + lr*12 + lh*4], Ahg + aoff);
            cpa16(&Al[so + lr*12 + lh*4], Alg + aoff);
            cpa16(&Wh[so + lr*12 + lh*4], Whg + woff);
            cpa16(&Wl[so + lr*12 + lh*4], Wlg + woff);
        }
        CPA_COMMIT;

        const int sc = st * 1536;
        const unsigned* sAh = Ah + sc; const unsigned* sAl = Al + sc;
        const unsigned* sWh = Wh + sc; const unsigned* sWl = Wl + sc;
        unsigned afh[4][4], afl[4][4], bfh[4][2], bfl[4][2];
        #pragma unroll
        for (int mt = 0; mt < 4; mt++) {
            ldsm4(afh[mt], &sAh[(arow + mt*16)*12 + aword]);
            ldsm4(afl[mt], &sAl[(arow + mt*16)*12 + aword]);
        }
        #pragma unroll
        for (int nt = 0; nt < 4; nt++) {
            ldsm2(bfh[nt], &sWh[(brow + nt*8)*12 + bword]);
            ldsm2(bfl[nt], &sWl[(brow + nt*8)*12 + bword]);
        }
        #pragma unroll
        for (int mt = 0; mt < 4; mt++)
            #pragma unroll
            for (int nt = 0; nt < 4; nt++) {
                mma16816(acc[mt][nt], afh[mt], bfh[nt]);
                mma16816(acc[mt][nt], afh[mt], bfl[nt]);
                mma16816(acc[mt][nt], afl[mt], bfh[nt]);
            }
    }

    #pragma unroll
    for (int mt = 0; mt < 4; mt++)
        #pragma unroll
        for (int nt = 0; nt < 4; nt++) {
            const float* a = acc[mt][nt];
            int rbase = row0 + wm*64 + mt*16 + qr;
            int cbase = col0 + wn*32 + nt*8 + qk*2;
            float bv0 = bias[cbase], bv1 = bias[cbase + 1];
            #pragma unroll
            for (int hf = 0; hf < 2; hf++) {
                int r = rbase + hf*8;
                float v0 = a[hf*2+0] + bv0;
                float v1 = a[hf*2+1] + bv1;
                size_t idx = (size_t)r * ldc + cbase;
                if constexpr (EPI == 0 || EPI == 1) {
                    if constexpr (EPI == 1) { v0 = fmaxf(v0, 0.f); v1 = fmaxf(v1, 0.f); }
                    unsigned pl, ph = pksplit(v0, v1, pl);
                    *(unsigned*)(Ch + idx) = ph;
                    *(unsigned*)(Cl + idx) = pl;
                } else if constexpr (EPI == 2) {
                    float2 o; o.x = 0.5f*v0; o.y = 0.5f*v1;
                    *(float2*)(Cf + idx) = o;
                } else {
                    float fm = 0.5f * fmask[r];
                    float2 cur = *(float2*)(Cf + idx);
                    cur.x += fm*v0; cur.y += fm*v1;
                    *(float2*)(Cf + idx) = cur;
                }
            }
        }
}

template<int EPI>
__global__ __launch_bounds__(256) void gemm_tc(
    const __nv_bfloat16* __restrict__ Ahg, const __nv_bfloat16* __restrict__ Alg,
    const __nv_bfloat16* __restrict__ Whg, const __nv_bfloat16* __restrict__ Wlg,
    const float* __restrict__ bias, const float* __restrict__ fmask,
    float* __restrict__ Cf, __nv_bfloat16* __restrict__ Ch, __nv_bfloat16* __restrict__ Cl,
    int K, int lda, int ldw, int ldc)
{
    extern __shared__ unsigned sm[];
    gemm_body<EPI>(sm, blockIdx.x, blockIdx.y, Ahg, Alg, Whg, Wlg, bias, fmask,
                   Cf, Ch, Cl, K, lda, ldw, ldc);
}
#define GEMM_SMEM 49152

// ---------------------------------------------------------------------------
// Fat kernel: flash (blocks [0,512), TWO independent 64-row Q items per block,
// one per 128-thread half with private smem + named barrier) + residual GEMM
// tiles (blocks [512,768)) back-filling the tail.
// ---------------------------------------------------------------------------
#define KS_STRIDE 36
#define KS_WORDS (128*KS_STRIDE)
#define HALF_WORDS (4*KS_WORDS)
#define FL_SMEM_BYTES (2*HALF_WORDS*4)   // 147456

__global__ void __launch_bounds__(256, 1) flash_fat(
    const __nv_bfloat16* __restrict__ qh, const __nv_bfloat16* __restrict__ ql,
    const float* __restrict__ slw, const float* __restrict__ fmask,
    __nv_bfloat16* __restrict__ Hh, __nv_bfloat16* __restrict__ Hl,
    const __nv_bfloat16* __restrict__ xh, const __nv_bfloat16* __restrict__ xl,
    const __nv_bfloat16* __restrict__ wrh, const __nv_bfloat16* __restrict__ wrl,
    const float* __restrict__ br, float* __restrict__ out)
{
    extern __shared__ unsigned smem[];
    const int bid = blockIdx.x;

    if (bid >= 512) {
        int idx = bid - 512;
        gemm_body<2>(smem, idx & 3, idx >> 2, xh, xl, wrh, wrl, br, fmask,
                     out, (__nv_bfloat16*)0, (__nv_bfloat16*)0, CD, CD, CD, CO);
        return;
    }

    const int tid = threadIdx.x;
    const int half = tid >> 7;            // 0 or 1
    const int htid = tid & 127;
    const int barid = 1 + half;
    unsigned* hs = smem + half * HALF_WORDS;
    unsigned* Ksh = hs;
    unsigned* Ksl = hs + KS_WORDS;
    unsigned* Vsh = hs + 2*KS_WORDS;
    unsigned* Vsl = hs + 3*KS_WORDS;

    const int item = bid*2 + half;        // [0,1024)
    const int qt6 = item & 15;            // 64-row Q tile index
    const int z = item >> 4;
    const int b = z >> 3, h = z & 7;
    const int lane = tid & 31;
    const int hwid = (tid >> 5) & 3;      // warp within half (0..3)
    const int qr = lane >> 2, qk = lane & 3;

    const size_t bhq = (size_t)b*CN*QKVLD + h*CHD;
    const size_t bhk = bhq + CO;
    const size_t bhv = bhq + 2*CO;

    const int krow  = ((lane >> 4) & 1) * 8 + (lane & 7);
    const int kword = ((lane >> 3) & 1) * 4;
    const int vrow  = lane & 15;
    const int vword = (lane >> 4) * 4;

    // ---- stage this half's 64-row Q tile through its K buffer ----
    {
        int qrow = htid >> 1, lq = htid & 1;
        size_t qoff = bhq + (size_t)(qt6*64 + qrow)*QKVLD + lq*32;
        #pragma unroll
        for (int i = 0; i < 4; i++) {
            *(uint4*)&Ksh[qrow*KS_STRIDE + lq*16 + i*4] = *(const uint4*)(qh + qoff + i*8);
            *(uint4*)&Ksl[qrow*KS_STRIDE + lq*16 + i*4] = *(const uint4*)(ql + qoff + i*8);
        }
    }
    hbar(barid);
    unsigned qfh[4][4], qfl[4][4];
    #pragma unroll
    for (int kw = 0; kw < 4; kw++) {
        int r0 = (hwid*16 + qr) * KS_STRIDE + kw*8;
        int r8 = (hwid*16 + qr + 8) * KS_STRIDE + kw*8;
        qfh[kw][0] = Ksh[r0 + qk];     qfh[kw][1] = Ksh[r8 + qk];
        qfh[kw][2] = Ksh[r0 + qk + 4]; qfh[kw][3] = Ksh[r8 + qk + 4];
        qfl[kw][0] = Ksl[r0 + qk];     qfl[kw][1] = Ksl[r8 + qk];
        qfl[kw][2] = Ksl[r0 + qk + 4]; qfl[kw][3] = Ksl[r8 + qk + 4];
    }
    hbar(barid);

    const float wd = slw[h];
    float o[8][4];
    #pragma unroll
    for (int i = 0; i < 8; i++)
        #pragma unroll
        for (int j = 0; j < 4; j++) o[i][j] = 0.f;
    float m0 = -1e30f, m1 = -1e30f, l0 = 0.f, l1 = 0.f;

    const int dkt = qt6 >> 1;             // K tile containing this Q tile's diagonal
    const int drow = (qt6 & 1) * 64;      // row offset of diagonal inside that tile

    for (int kt = 0; kt < 8; kt++) {
        // ---- load K + V tiles (128 rows each, one row per thread) ----
        {
            size_t koff = bhk + (size_t)(kt*128 + htid)*QKVLD;
            size_t voff = bhv + (size_t)(kt*128 + htid)*QKVLD;
            unsigned* kd_h = &Ksh[htid*KS_STRIDE];
            unsigned* kd_l = &Ksl[htid*KS_STRIDE];
            unsigned* vd_h = &Vsh[htid*KS_STRIDE];
            unsigned* vd_l = &Vsl[htid*KS_STRIDE];
            #pragma unroll
            for (int i = 0; i < 8; i++) {
                *(uint4*)&kd_h[i*4] = *(const uint4*)(qh + koff + i*8);
                *(uint4*)&kd_l[i*4] = *(const uint4*)(ql + koff + i*8);
                *(uint4*)&vd_h[i*4] = *(const uint4*)(qh + voff + i*8);
                *(uint4*)&vd_l[i*4] = *(const uint4*)(ql + voff + i*8);
            }
        }
        hbar(barid);

        const float* fmc = fmask + b*CN + kt*128;

        // ---- S = Q K^T (bf16x3, ldmatrix K in nt pairs) ----
        float s[16][4];
        #pragma unroll
        for (int nt = 0; nt < 16; nt++)
            #pragma unroll
            for (int i = 0; i < 4; i++) s[nt][i] = 0.f;
        #pragma unroll
        for (int ntp = 0; ntp < 8; ntp++) {
            float* sA = s[2*ntp];
            float* sB = s[2*ntp + 1];
            #pragma unroll
            for (int kw = 0; kw < 4; kw++) {
                unsigned kh[4], kl[4];
                ldsm4(kh, &Ksh[(ntp*16 + krow)*KS_STRIDE + kw*8 + kword]);
                ldsm4(kl, &Ksl[(ntp*16 + krow)*KS_STRIDE + kw*8 + kword]);
                mma16816(sA, qfh[kw], kh + 0);
                mma16816(sA, qfh[kw], kl + 0);
                mma16816(sA, qfl[kw], kh + 0);
                mma16816(sB, qfh[kw], kh + 2);
                mma16816(sB, qfh[kw], kl + 2);
                mma16816(sB, qfl[kw], kh + 2);
            }
        }

        // ---- scale + diag + col-mask, online softmax ----
        const int lr0 = hwid*16 + qr, lr1 = lr0 + 8;
        float tmax0 = -3e38f, tmax1 = -3e38f;
        #pragma unroll
        for (int nt = 0; nt < 16; nt++) {
            int c0 = nt*8 + qk*2;
            float2 cmv = *(const float2*)(fmc + c0);
            float v0 = s[nt][0]*0.125f, v1 = s[nt][1]*0.125f;
            float v2 = s[nt][2]*0.125f, v3 = s[nt][3]*0.125f;
            if (kt == dkt) {
                if (drow + lr0 == c0)     v0 += wd;
                if (drow + lr0 == c0 + 1) v1 += wd;
                if (drow + lr1 == c0)     v2 += wd;
                if (drow + lr1 == c0 + 1) v3 += wd;
            }
            if (cmv.x == 0.f) { v0 = -1e6f; v2 = -1e6f; }
            if (cmv.y == 0.f) { v1 = -1e6f; v3 = -1e6f; }
            s[nt][0] = v0; s[nt][1] = v1; s[nt][2] = v2; s[nt][3] = v3;
            tmax0 = fmaxf(tmax0, fmaxf(v0, v1));
            tmax1 = fmaxf(tmax1, fmaxf(v2, v3));
        }
        #pragma unroll
        for (int off = 1; off <= 2; off <<= 1) {
            tmax0 = fmaxf(tmax0, __shfl_xor_sync(0xffffffffu, tmax0, off));
            tmax1 = fmaxf(tmax1, __shfl_xor_sync(0xffffffffu, tmax1, off));
        }
        float mn0 = fmaxf(m0, tmax0), mn1 = fmaxf(m1, tmax1);
        float sc0 = __expf(m0 - mn0), sc1 = __expf(m1 - mn1);
        m0 = mn0; m1 = mn1;
        l0 *= sc0; l1 *= sc1;
        #pragma unroll
        for (int nt2 = 0; nt2 < 8; nt2++) {
            o[nt2][0] *= sc0; o[nt2][1] *= sc0;
            o[nt2][2] *= sc1; o[nt2][3] *= sc1;
        }
        float rs0 = 0.f, rs1 = 0.f;
        #pragma unroll
        for (int nt = 0; nt < 16; nt++) {
            float p0 = __expf(s[nt][0] - mn0);
            float p1 = __expf(s[nt][1] - mn0);
            float p2 = __expf(s[nt][2] - mn1);
            float p3 = __expf(s[nt][3] - mn1);
            rs0 += p0 + p1; rs1 += p2 + p3;
            s[nt][0] = p0; s[nt][1] = p1; s[nt][2] = p2; s[nt][3] = p3;
        }
        #pragma unroll
        for (int off = 1; off <= 2; off <<= 1) {
            rs0 += __shfl_xor_sync(0xffffffffu, rs0, off);
            rs1 += __shfl_xor_sync(0xffffffffu, rs1, off);
        }
        l0 += rs0; l1 += rs1;

        // ---- O += P V (bf16x3; pksplit P pack; ldmatrix.trans V) ----
        #pragma unroll
        for (int kk = 0; kk < 8; kk++) {
            const float* t0 = s[2*kk];
            const float* t1 = s[2*kk + 1];
            unsigned ah[4], al[4];
            ah[0] = pksplit(t0[0], t0[1], al[0]);
            ah[1] = pksplit(t0[2], t0[3], al[1]);
            ah[2] = pksplit(t1[0], t1[1], al[2]);
            ah[3] = pksplit(t1[2], t1[3], al[3]);
            #pragma unroll
            for (int ntp = 0; ntp < 4; ntp++) {
                unsigned vh[4], vl[4];
                ldsm4t(vh, &Vsh[(kk*16 + vrow)*KS_STRIDE + ntp*8 + vword]);
                ldsm4t(vl, &Vsl[(kk*16 + vrow)*KS_STRIDE + ntp*8 + vword]);
                mma16816(o[2*ntp],     ah, vh + 0);
                mma16816(o[2*ntp],     ah, vl + 0);
                mma16816(o[2*ntp],     al, vh + 0);
                mma16816(o[2*ntp + 1], ah, vh + 2);
                mma16816(o[2*ntp + 1], ah, vl + 2);
                mma16816(o[2*ntp + 1], al, vh + 2);
            }
        }
        hbar(barid);
    }

    // ---- epilogue: normalize, fmask, split-store merged-head H ----
    const int grow0 = b*CN + qt6*64 + hwid*16 + qr;
    const int grow1 = grow0 + 8;
    float f0 = fmask[grow0] / l0;
    float f1 = fmask[grow1] / l1;
    #pragma unroll
    for (int nt2 = 0; nt2 < 8; nt2++) {
        int col = h*CHD + nt2*8 + qk*2;
        size_t i0 = (size_t)grow0*CO + col;
        size_t i1 = (size_t)grow1*CO + col;
        unsigned pl0, ph0 = pksplit(o[nt2][0]*f0, o[nt2][1]*f0, pl0);
        unsigned pl1, ph1 = pksplit(o[nt2][2]*f1, o[nt2][3]*f1, pl1);
        *(unsigned*)(Hh + i0) = ph0;
        *(unsigned*)(Hl + i0) = pl0;
        *(unsigned*)(Hh + i1) = ph1;
        *(unsigned*)(Hl + i1) = pl1;
    }
}

// ---------------------------------------------------------------------------
extern "C" void kernel_launch(void* const* d_in, const int* in_sizes, int n_in,
                              void* d_out, int out_size)
{
    const float* x = 0;  const unsigned char* mask_raw = 0;
    const float* slw = 0; const float* qkv_w = 0; const float* qkv_b = 0;
    const float* wbig[3] = {0,0,0}; const float* bsm[3] = {0,0,0};
    int nw = 0, nb = 0;

    for (int i = 0; i < n_in; i++) {
        switch (in_sizes[i]) {
            case 4194304: x        = (const float*)d_in[i]; break;
            case 8388608: /* adj unused */                  break;
            case 8192:    mask_raw = (const unsigned char*)d_in[i]; break;
            case 8:       slw      = (const float*)d_in[i]; break;
            case 786432:  qkv_w    = (const float*)d_in[i]; break;
            case 1536:    qkv_b    = (const float*)d_in[i]; break;
            case 262144:  if (nw < 3) wbig[nw++] = (const float*)d_in[i]; break;
            case 512:     if (nb < 3) bsm[nb++]  = (const float*)d_in[i]; break;
            default: break;
        }
    }
    const float *w1 = wbig[0], *w2 = wbig[1], *wr = wbig[2];
    const float *b1 = bsm[0],  *b2 = bsm[1],  *br = bsm[2];
    float* out = (float*)d_out;

    void *pf, *pxh, *pxl, *pqwh, *pqwl, *pw1h, *pw1l, *pw2h, *pw2l, *pwrh, *pwrl;
    void *pqh, *pql, *pHh, *pHl, *pTh, *pTl;
    cudaGetSymbolAddress(&pf,   g_fmask);
    cudaGetSymbolAddress(&pxh,  g_xh);   cudaGetSymbolAddress(&pxl,  g_xl);
    cudaGetSymbolAddress(&pqwh, g_qwh);  cudaGetSymbolAddress(&pqwl, g_qwl);
    cudaGetSymbolAddress(&pw1h, g_w1h);  cudaGetSymbolAddress(&pw1l, g_w1l);
    cudaGetSymbolAddress(&pw2h, g_w2h);  cudaGetSymbolAddress(&pw2l, g_w2l);
    cudaGetSymbolAddress(&pwrh, g_wrh);  cudaGetSymbolAddress(&pwrl, g_wrl);
    cudaGetSymbolAddress(&pqh,  g_qh);   cudaGetSymbolAddress(&pql,  g_ql);
    cudaGetSymbolAddress(&pHh,  g_Hh);   cudaGetSymbolAddress(&pHl,  g_Hl);
    cudaGetSymbolAddress(&pTh,  g_Th);   cudaGetSymbolAddress(&pTl,  g_Tl);

    float* fmp = (float*)pf;
    __nv_bfloat16 *xh=(__nv_bfloat16*)pxh, *xl=(__nv_bfloat16*)pxl;
    __nv_bfloat16 *qwh=(__nv_bfloat16*)pqwh, *qwl=(__nv_bfloat16*)pqwl;
    __nv_bfloat16 *w1h=(__nv_bfloat16*)pw1h, *w1l=(__nv_bfloat16*)pw1l;
    __nv_bfloat16 *w2h=(__nv_bfloat16*)pw2h, *w2l=(__nv_bfloat16*)pw2l;
    __nv_bfloat16 *wrh=(__nv_bfloat16*)pwrh, *wrl=(__nv_bfloat16*)pwrl;
    __nv_bfloat16 *qhp=(__nv_bfloat16*)pqh, *qlp=(__nv_bfloat16*)pql;
    __nv_bfloat16 *Hhp=(__nv_bfloat16*)pHh, *Hlp=(__nv_bfloat16*)pHl;
    __nv_bfloat16 *Thp=(__nv_bfloat16*)pTh, *Tlp=(__nv_bfloat16*)pTl;

    static int smem_set = 0;
    if (!smem_set) {
        cudaFuncSetAttribute(flash_fat, cudaFuncAttributeMaxDynamicSharedMemorySize,
                             FL_SMEM_BYTES);
        smem_set = 1;
    }

    // 0) mask convert + fused one-time splits
    mask_convert<<<1, 256>>>(mask_raw, fmp);
    split5<<<(SPLT+255)/256, 256>>>(x, qkv_w, w1, w2, wr,
                                    xh, xl, qwh, qwl, w1h, w1l, w2h, w2l, wrh, wrl);

    // 1) QKV = x @ qkv_w^T + qkv_b  -> split bf16
    gemm_tc<0><<<dim3(12, 64), 256, GEMM_SMEM>>>(xh, xl, qwh, qwl, qkv_b, fmp,
                                      (float*)0, qhp, qlp, CD, CD, CD, QKVLD);

    // 2-4) flash attention (2 items/block, split-half) + residual gemm tail-fill
    flash_fat<<<768, 256, FL_SMEM_BYTES>>>(qhp, qlp, slw, fmp, Hhp, Hlp,
                                           xh, xl, wrh, wrl, br, out);

    // 5) T = relu(H @ w1^T + b1) -> split bf16
    gemm_tc<1><<<dim3(4, 64), 256, GEMM_SMEM>>>(Hhp, Hlp, w1h, w1l, b1, fmp,
                                     (float*)0, Thp, Tlp, CO, CO, CO, CO);

    // 6) out += 0.5*fmask*(T @ w2^T + b2)   (out initialized by fat kernel)
    gemm_tc<3><<<dim3(4, 64), 256, GEMM_SMEM>>>(Thp, Tlp, w2h, w2l, b2, fmp,
                                     out, (__nv_bfloat16*)0, (__nv_bfloat16*)0, CO, CO, CO, CO);
}

// round 13
// speedup vs baseline: 1.1285x; 1.1285x over previous
#include <cuda_runtime.h>
#include <cuda_bf16.h>
#include <math.h>

// Problem constants
#define CB 8
#define CN 1024
#define CD 512
#define CO 512
#define CH 8
#define CHD 64
#define QKVLD 1536   // 3*O
#define MROWS (CB*CN) // 8192

// ---------------- scratch (static device allocations; no cudaMalloc) ----------
__device__ float g_fmask[MROWS];
__device__ __nv_bfloat16 g_xh[MROWS*CD],  g_xl[MROWS*CD];
__device__ __nv_bfloat16 g_qwh[QKVLD*CD], g_qwl[QKVLD*CD];
__device__ __nv_bfloat16 g_w1h[CO*CO], g_w1l[CO*CO];
__device__ __nv_bfloat16 g_w2h[CO*CO], g_w2l[CO*CO];
__device__ __nv_bfloat16 g_wrh[CO*CD], g_wrl[CO*CD];
__device__ __nv_bfloat16 g_qh[(size_t)MROWS*QKVLD], g_ql[(size_t)MROWS*QKVLD];
__device__ __nv_bfloat16 g_Hh[MROWS*CO], g_Hl[MROWS*CO];
__device__ __nv_bfloat16 g_Th[MROWS*CO], g_Tl[MROWS*CO];

// ---------------------------------------------------------------------------
__device__ __forceinline__ void bsplit(float v, __nv_bfloat16& h, __nv_bfloat16& l){
    h = __float2bfloat16(v);
    l = __float2bfloat16(v - __bfloat162float(h));
}
// Packed split: hi = bf16x2(v0,v1), lo = bf16x2 residuals (RN, bit-identical).
__device__ __forceinline__ unsigned pksplit(float v0, float v1, unsigned& lo){
    unsigned hi;
    asm("cvt.rn.bf16x2.f32 %0, %1, %2;" : "=r"(hi) : "f"(v1), "f"(v0));
    float h0 = __uint_as_float(hi << 16);
    float h1 = __uint_as_float(hi & 0xffff0000u);
    asm("cvt.rn.bf16x2.f32 %0, %1, %2;" : "=r"(lo) : "f"(v1 - h1), "f"(v0 - h0));
    return hi;
}
__device__ __forceinline__ void mma16816(float* c, const unsigned* a, const unsigned* b){
    asm volatile("mma.sync.aligned.m16n8k16.row.col.f32.bf16.bf16.f32 "
        "{%0,%1,%2,%3}, {%4,%5,%6,%7}, {%8,%9}, {%0,%1,%2,%3};"
        : "+f"(c[0]), "+f"(c[1]), "+f"(c[2]), "+f"(c[3])
        : "r"(a[0]), "r"(a[1]), "r"(a[2]), "r"(a[3]), "r"(b[0]), "r"(b[1]));
}
__device__ __forceinline__ void ldsm4(unsigned* r, const void* p){
    unsigned a = (unsigned)__cvta_generic_to_shared(p);
    asm volatile("ldmatrix.sync.aligned.m8n8.x4.shared.b16 {%0,%1,%2,%3}, [%4];"
        : "=r"(r[0]), "=r"(r[1]), "=r"(r[2]), "=r"(r[3]) : "r"(a));
}
__device__ __forceinline__ void ldsm4t(unsigned* r, const void* p){
    unsigned a = (unsigned)__cvta_generic_to_shared(p);
    asm volatile("ldmatrix.sync.aligned.m8n8.x4.trans.shared.b16 {%0,%1,%2,%3}, [%4];"
        : "=r"(r[0]), "=r"(r[1]), "=r"(r[2]), "=r"(r[3]) : "r"(a));
}
__device__ __forceinline__ void ldsm2(unsigned* r, const void* p){
    unsigned a = (unsigned)__cvta_generic_to_shared(p);
    asm volatile("ldmatrix.sync.aligned.m8n8.x2.shared.b16 {%0,%1}, [%2];"
        : "=r"(r[0]), "=r"(r[1]) : "r"(a));
}
__device__ __forceinline__ void cpa16(void* dst_smem, const void* src){
    unsigned sa = (unsigned)__cvta_generic_to_shared(dst_smem);
    asm volatile("cp.async.cg.shared.global [%0], [%1], 16;" :: "r"(sa), "l"(src));
}
#define CPA_COMMIT asm volatile("cp.async.commit_group;")
#define CPA_WAIT0  asm volatile("cp.async.wait_group 0;")

// ---------------------------------------------------------------------------
// Mask conversion (dtype auto-detect; bench data treated strictly as data)
// ---------------------------------------------------------------------------
__global__ void mask_convert(const unsigned char* __restrict__ raw,
                             float* __restrict__ fmask)
{
    __shared__ int s_m1, s_m23, s_gt1;
    int t = threadIdx.x;
    if (t == 0) { s_m1 = 0; s_m23 = 0; s_gt1 = 0; }
    __syncthreads();
    int m1 = 0, m23 = 0, g = 0;
    for (int i = t; i < MROWS; i += 256) {
        unsigned char v = raw[i];
        if (v) {
            int p = i & 3;
            if (p == 1) m1 = 1;
            if (p >= 2) m23 = 1;
            if (v > 1) g = 1;
        }
    }
    if (m1)  atomicOr(&s_m1, 1);
    if (m23) atomicOr(&s_m23, 1);
    if (g)   atomicOr(&s_gt1, 1);
    __syncthreads();
    int mis = s_m1 | s_m23;
    int mode;
    if (!mis)            mode = 0;
    else if (!s_gt1)     mode = 1;
    else if (s_m1)       mode = 3;
    else                 mode = 2;
    for (int i = t; i < MROWS; i += 256) {
        float f;
        if (mode == 0)      f = (((const int*)raw)[i]            != 0)   ? 1.f : 0.f;
        else if (mode == 1) f = (raw[i]                          != 0)   ? 1.f : 0.f;
        else if (mode == 2) f = (((const float*)raw)[i]          != 0.f) ? 1.f : 0.f;
        else                f = (((const unsigned short*)raw)[i] != 0)   ? 1.f : 0.f;
        fmask[i] = f;
    }
}

// ---------------------------------------------------------------------------
// Fused splitter: x, qkv_w, w1, w2, wr in one launch.
// ---------------------------------------------------------------------------
#define SPL0 (MROWS*CD)
#define SPL1 (QKVLD*CD)
#define SPL2 (CO*CO)
#define SPL3 (CO*CO)
#define SPL4 (CO*CD)
#define SPLT (SPL0+SPL1+SPL2+SPL3+SPL4)
__global__ void split5(
    const float* __restrict__ s0, const float* __restrict__ s1,
    const float* __restrict__ s2, const float* __restrict__ s3,
    const float* __restrict__ s4,
    __nv_bfloat16* __restrict__ h0, __nv_bfloat16* __restrict__ l0,
    __nv_bfloat16* __restrict__ h1, __nv_bfloat16* __restrict__ l1,
    __nv_bfloat16* __restrict__ h2, __nv_bfloat16* __restrict__ l2,
    __nv_bfloat16* __restrict__ h3, __nv_bfloat16* __restrict__ l3,
    __nv_bfloat16* __restrict__ h4, __nv_bfloat16* __restrict__ l4)
{
    int i = blockIdx.x * 256 + threadIdx.x;
    if (i >= SPLT) return;
    const float* s; __nv_bfloat16 *h, *l; int j = i;
    if (j < SPL0)                { s = s0; h = h0; l = l0; }
    else if ((j -= SPL0) < SPL1) { s = s1; h = h1; l = l1; }
    else if ((j -= SPL1) < SPL2) { s = s2; h = h2; l = l2; }
    else if ((j -= SPL2) < SPL3) { s = s3; h = h3; l = l3; }
    else { j -= SPL3;              s = s4; h = h4; l = l4; }
    __nv_bfloat16 hh, ll;
    bsplit(s[j], hh, ll);
    h[j] = hh; l[j] = ll;
}

// ---------------------------------------------------------------------------
// Tensor-core NT GEMM body (bf16x3), BK=32, cp.async double-buffered, ldmatrix.
// Dynamic smem: Ah[2][2560] | Al | Wh | Wl = 20480 u32 = 81920 B.
// Row stride 20 u32 (conflict-free for ldmatrix: banks {0,20,8,28,16,4,24,12}).
// 128x128 tile, 256 thr (8 warps = 2m x 4n).
// EPI: 0 split-store; 1 relu+split-store; 2 Cf=0.5v; 3 Cf+=0.5*fmask[m]*v
// ---------------------------------------------------------------------------
#define GW 20
#define GSTG (128*GW)   // 2560 u32 per stage per array
#define GEMM_SMEM (8*GSTG*4)  // 81920

template<int EPI>
__device__ __forceinline__ void gemm_body(
    unsigned* sm, int bx, int by,
    const __nv_bfloat16* __restrict__ Ahg, const __nv_bfloat16* __restrict__ Alg,
    const __nv_bfloat16* __restrict__ Whg, const __nv_bfloat16* __restrict__ Wlg,
    const float* __restrict__ bias, const float* __restrict__ fmask,
    float* __restrict__ Cf, __nv_bfloat16* __restrict__ Ch, __nv_bfloat16* __restrict__ Cl,
    int K, int lda, int ldw, int ldc)
{
    unsigned* Ah = sm;
    unsigned* Al = sm + 2*GSTG;
    unsigned* Wh = sm + 4*GSTG;
    unsigned* Wl = sm + 6*GSTG;
    const int tid = threadIdx.x;
    const int lane = tid & 31, wid = tid >> 5;
    const int wm = wid & 1, wn = wid >> 1;
    const int row0 = by * 128, col0 = bx * 128;
    const int lr = tid >> 1, lq = tid & 1;
    const int qr = lane >> 2, qk = lane & 3;

    const int arow  = wm*64 + (lane & 7) + ((lane >> 3) & 1) * 8;
    const int aword = ((lane >> 4) & 1) * 4;
    const int brow  = wn*32 + (lane & 7);
    const int bword = ((lane >> 3) & 1) * 4;

    float acc[4][4][4];
    #pragma unroll
    for (int mt = 0; mt < 4; mt++)
        #pragma unroll
        for (int nt = 0; nt < 4; nt++)
            #pragma unroll
            for (int i = 0; i < 4; i++) acc[mt][nt][i] = 0.f;

    {
        size_t aoff = (size_t)(row0 + lr) * lda + lq * 16;
        size_t woff = (size_t)(col0 + lr) * ldw + lq * 16;
        #pragma unroll
        for (int j = 0; j < 2; j++) {
            cpa16(&Ah[lr*GW + lq*8 + j*4], Ahg + aoff + j*8);
            cpa16(&Al[lr*GW + lq*8 + j*4], Alg + aoff + j*8);
            cpa16(&Wh[lr*GW + lq*8 + j*4], Whg + woff + j*8);
            cpa16(&Wl[lr*GW + lq*8 + j*4], Wlg + woff + j*8);
        }
    }
    CPA_COMMIT;

    int st = 0;
    for (int k0 = 0; k0 < K; k0 += 32, st ^= 1) {
        CPA_WAIT0;
        __syncthreads();
        if (k0 + 32 < K) {
            const int so = (st^1) * GSTG;
            size_t aoff = (size_t)(row0 + lr) * lda + k0 + 32 + lq * 16;
            size_t woff = (size_t)(col0 + lr) * ldw + k0 + 32 + lq * 16;
            #pragma unroll
            for (int j = 0; j < 2; j++) {
                cpa16(&Ah[so + lr*GW + lq*8 + j*4], Ahg + aoff + j*8);
                cpa16(&Al[so + lr*GW + lq*8 + j*4], Alg + aoff + j*8);
                cpa16(&Wh[so + lr*GW + lq*8 + j*4], Whg + woff + j*8);
                cpa16(&Wl[so + lr*GW + lq*8 + j*4], Wlg + woff + j*8);
            }
        }
        CPA_COMMIT;

        const int sc = st * GSTG;
        #pragma unroll
        for (int g = 0; g < 2; g++) {
            unsigned afh[4][4], afl[4][4], bfh[4][2], bfl[4][2];
            #pragma unroll
            for (int mt = 0; mt < 4; mt++) {
                ldsm4(afh[mt], &Ah[sc + (arow + mt*16)*GW + g*8 + aword]);
                ldsm4(afl[mt], &Al[sc + (arow + mt*16)*GW + g*8 + aword]);
            }
            #pragma unroll
            for (int nt = 0; nt < 4; nt++) {
                ldsm2(bfh[nt], &Wh[sc + (brow + nt*8)*GW + g*8 + bword]);
                ldsm2(bfl[nt], &Wl[sc + (brow + nt*8)*GW + g*8 + bword]);
            }
            #pragma unroll
            for (int mt = 0; mt < 4; mt++)
                #pragma unroll
                for (int nt = 0; nt < 4; nt++) {
                    mma16816(acc[mt][nt], afh[mt], bfh[nt]);
                    mma16816(acc[mt][nt], afh[mt], bfl[nt]);
                    mma16816(acc[mt][nt], afl[mt], bfh[nt]);
                }
        }
    }

    #pragma unroll
    for (int mt = 0; mt < 4; mt++)
        #pragma unroll
        for (int nt = 0; nt < 4; nt++) {
            const float* a = acc[mt][nt];
            int rbase = row0 + wm*64 + mt*16 + qr;
            int cbase = col0 + wn*32 + nt*8 + qk*2;
            float bv0 = bias[cbase], bv1 = bias[cbase + 1];
            #pragma unroll
            for (int hf = 0; hf < 2; hf++) {
                int r = rbase + hf*8;
                float v0 = a[hf*2+0] + bv0;
                float v1 = a[hf*2+1] + bv1;
                size_t idx = (size_t)r * ldc + cbase;
                if constexpr (EPI == 0 || EPI == 1) {
                    if constexpr (EPI == 1) { v0 = fmaxf(v0, 0.f); v1 = fmaxf(v1, 0.f); }
                    unsigned pl, ph = pksplit(v0, v1, pl);
                    *(unsigned*)(Ch + idx) = ph;
                    *(unsigned*)(Cl + idx) = pl;
                } else if constexpr (EPI == 2) {
                    float2 o; o.x = 0.5f*v0; o.y = 0.5f*v1;
                    *(float2*)(Cf + idx) = o;
                } else {
                    float fm = 0.5f * fmask[r];
                    float2 cur = *(float2*)(Cf + idx);
                    cur.x += fm*v0; cur.y += fm*v1;
                    *(float2*)(Cf + idx) = cur;
                }
            }
        }
}

template<int EPI>
__global__ __launch_bounds__(256) void gemm_tc(
    const __nv_bfloat16* __restrict__ Ahg, const __nv_bfloat16* __restrict__ Alg,
    const __nv_bfloat16* __restrict__ Whg, const __nv_bfloat16* __restrict__ Wlg,
    const float* __restrict__ bias, const float* __restrict__ fmask,
    float* __restrict__ Cf, __nv_bfloat16* __restrict__ Ch, __nv_bfloat16* __restrict__ Cl,
    int K, int lda, int ldw, int ldc)
{
    extern __shared__ unsigned sm[];
    gemm_body<EPI>(sm, blockIdx.x, blockIdx.y, Ahg, Alg, Whg, Wlg, bias, fmask,
                   Cf, Ch, Cl, K, lda, ldw, ldc);
}

// ---------------------------------------------------------------------------
// Fat kernel (R11 form): flash (blocks [0,512), one 128-row Q tile per block)
// + residual GEMM tiles (blocks [512,768)) back-filling flash's tail.
// ---------------------------------------------------------------------------
#define KS_STRIDE 36
#define KS_WORDS (128*KS_STRIDE)
#define FL_WORDS (4*KS_WORDS)            // flash branch usage (73728 B)
#define FAT_SMEM (GEMM_SMEM)             // 81920 >= 73728

__global__ void __launch_bounds__(256, 1) flash_fat(
    const __nv_bfloat16* __restrict__ qh, const __nv_bfloat16* __restrict__ ql,
    const float* __restrict__ slw, const float* __restrict__ fmask,
    __nv_bfloat16* __restrict__ Hh, __nv_bfloat16* __restrict__ Hl,
    const __nv_bfloat16* __restrict__ xh, const __nv_bfloat16* __restrict__ xl,
    const __nv_bfloat16* __restrict__ wrh, const __nv_bfloat16* __restrict__ wrl,
    const float* __restrict__ br, float* __restrict__ out)
{
    extern __shared__ unsigned smem[];
    const int bid = blockIdx.x;

    if (bid >= 512) {
        int idx = bid - 512;
        gemm_body<2>(smem, idx & 3, idx >> 2, xh, xl, wrh, wrl, br, fmask,
                     out, (__nv_bfloat16*)0, (__nv_bfloat16*)0, CD, CD, CD, CO);
        return;
    }

    unsigned* Ksh = smem;
    unsigned* Ksl = smem + KS_WORDS;
    unsigned* Vsh = smem + 2*KS_WORDS;
    unsigned* Vsl = smem + 3*KS_WORDS;

    const int qt = bid & 7, z = bid >> 3;
    const int b = z >> 3, h = z & 7;
    const int tid = threadIdx.x;
    const int lane = tid & 31, wid = tid >> 5;
    const int qr = lane >> 2, qk = lane & 3;

    const size_t bhq = (size_t)b*CN*QKVLD + h*CHD;
    const size_t bhk = bhq + CO;
    const size_t bhv = bhq + 2*CO;

    const int lrow = tid >> 1, lq = tid & 1;
    const int krow  = ((lane >> 4) & 1) * 8 + (lane & 7);
    const int kword = ((lane >> 3) & 1) * 4;
    const int vrow  = lane & 15;
    const int vword = (lane >> 4) * 4;

    // ---- stage Q tile through K buffer, pull fragments ----
    {
        size_t qoff = bhq + (size_t)(qt*128 + lrow)*QKVLD + lq*32;
        #pragma unroll
        for (int i = 0; i < 4; i++) {
            *(uint4*)&Ksh[lrow*KS_STRIDE + lq*16 + i*4] = *(const uint4*)(qh + qoff + i*8);
            *(uint4*)&Ksl[lrow*KS_STRIDE + lq*16 + i*4] = *(const uint4*)(ql + qoff + i*8);
        }
    }
    __syncthreads();
    unsigned qfh[4][4], qfl[4][4];
    #pragma unroll
    for (int kw = 0; kw < 4; kw++) {
        int r0 = (wid*16 + qr) * KS_STRIDE + kw*8;
        int r8 = (wid*16 + qr + 8) * KS_STRIDE + kw*8;
        qfh[kw][0] = Ksh[r0 + qk];     qfh[kw][1] = Ksh[r8 + qk];
        qfh[kw][2] = Ksh[r0 + qk + 4]; qfh[kw][3] = Ksh[r8 + qk + 4];
        qfl[kw][0] = Ksl[r0 + qk];     qfl[kw][1] = Ksl[r8 + qk];
        qfl[kw][2] = Ksl[r0 + qk + 4]; qfl[kw][3] = Ksl[r8 + qk + 4];
    }
    __syncthreads();

    const float wd = slw[h];
    float o[8][4];
    #pragma unroll
    for (int i = 0; i < 8; i++)
        #pragma unroll
        for (int j = 0; j < 4; j++) o[i][j] = 0.f;
    float m0 = -1e30f, m1 = -1e30f, l0 = 0.f, l1 = 0.f;

    for (int kt = 0; kt < 8; kt++) {
        {
            size_t koff = bhk + (size_t)(kt*128 + lrow)*QKVLD + lq*32;
            size_t voff = bhv + (size_t)(kt*128 + lrow)*QKVLD + lq*32;
            #pragma unroll
            for (int i = 0; i < 4; i++) {
                *(uint4*)&Ksh[lrow*KS_STRIDE + lq*16 + i*4] = *(const uint4*)(qh + koff + i*8);
                *(uint4*)&Ksl[lrow*KS_STRIDE + lq*16 + i*4] = *(const uint4*)(ql + koff + i*8);
                *(uint4*)&Vsh[lrow*KS_STRIDE + lq*16 + i*4] = *(const uint4*)(qh + voff + i*8);
                *(uint4*)&Vsl[lrow*KS_STRIDE + lq*16 + i*4] = *(const uint4*)(ql + voff + i*8);
            }
        }
        __syncthreads();

        const float* fmc = fmask + b*CN + kt*128;

        // ---- S = Q K^T (bf16x3, ldmatrix K in nt pairs) ----
        float s[16][4];
        #pragma unroll
        for (int nt = 0; nt < 16; nt++)
            #pragma unroll
            for (int i = 0; i < 4; i++) s[nt][i] = 0.f;
        #pragma unroll
        for (int ntp = 0; ntp < 8; ntp++) {
            float* sA = s[2*ntp];
            float* sB = s[2*ntp + 1];
            #pragma unroll
            for (int kw = 0; kw < 4; kw++) {
                unsigned kh[4], kl[4];
                ldsm4(kh, &Ksh[(ntp*16 + krow)*KS_STRIDE + kw*8 + kword]);
                ldsm4(kl, &Ksl[(ntp*16 + krow)*KS_STRIDE + kw*8 + kword]);
                mma16816(sA, qfh[kw], kh + 0);
                mma16816(sA, qfh[kw], kl + 0);
                mma16816(sA, qfl[kw], kh + 0);
                mma16816(sB, qfh[kw], kh + 2);
                mma16816(sB, qfh[kw], kl + 2);
                mma16816(sB, qfl[kw], kh + 2);
            }
        }

        // ---- scale + diag + col-mask, online softmax ----
        const int lr0 = wid*16 + qr, lr1 = lr0 + 8;
        float tmax0 = -3e38f, tmax1 = -3e38f;
        #pragma unroll
        for (int nt = 0; nt < 16; nt++) {
            int c0 = nt*8 + qk*2;
            float2 cmv = *(const float2*)(fmc + c0);
            float v0 = s[nt][0]*0.125f, v1 = s[nt][1]*0.125f;
            float v2 = s[nt][2]*0.125f, v3 = s[nt][3]*0.125f;
            if (qt == kt) {
                if (lr0 == c0)     v0 += wd;
                if (lr0 == c0 + 1) v1 += wd;
                if (lr1 == c0)     v2 += wd;
                if (lr1 == c0 + 1) v3 += wd;
            }
            if (cmv.x == 0.f) { v0 = -1e6f; v2 = -1e6f; }
            if (cmv.y == 0.f) { v1 = -1e6f; v3 = -1e6f; }
            s[nt][0] = v0; s[nt][1] = v1; s[nt][2] = v2; s[nt][3] = v3;
            tmax0 = fmaxf(tmax0, fmaxf(v0, v1));
            tmax1 = fmaxf(tmax1, fmaxf(v2, v3));
        }
        #pragma unroll
        for (int off = 1; off <= 2; off <<= 1) {
            tmax0 = fmaxf(tmax0, __shfl_xor_sync(0xffffffffu, tmax0, off));
            tmax1 = fmaxf(tmax1, __shfl_xor_sync(0xffffffffu, tmax1, off));
        }
        float mn0 = fmaxf(m0, tmax0), mn1 = fmaxf(m1, tmax1);
        float sc0 = __expf(m0 - mn0), sc1 = __expf(m1 - mn1);
        m0 = mn0; m1 = mn1;
        l0 *= sc0; l1 *= sc1;
        #pragma unroll
        for (int nt2 = 0; nt2 < 8; nt2++) {
            o[nt2][0] *= sc0; o[nt2][1] *= sc0;
            o[nt2][2] *= sc1; o[nt2][3] *= sc1;
        }
        float rs0 = 0.f, rs1 = 0.f;
        #pragma unroll
        for (int nt = 0; nt < 16; nt++) {
            float p0 = __expf(s[nt][0] - mn0);
            float p1 = __expf(s[nt][1] - mn0);
            float p2 = __expf(s[nt][2] - mn1);
            float p3 = __expf(s[nt][3] - mn1);
            rs0 += p0 + p1; rs1 += p2 + p3;
            s[nt][0] = p0; s[nt][1] = p1; s[nt][2] = p2; s[nt][3] = p3;
        }
        #pragma unroll
        for (int off = 1; off <= 2; off <<= 1) {
            rs0 += __shfl_xor_sync(0xffffffffu, rs0, off);
            rs1 += __shfl_xor_sync(0xffffffffu, rs1, off);
        }
        l0 += rs0; l1 += rs1;

        // ---- O += P V (bf16x3; pksplit P pack; ldmatrix.trans V) ----
        #pragma unroll
        for (int kk = 0; kk < 8; kk++) {
            const float* t0 = s[2*kk];
            const float* t1 = s[2*kk + 1];
            unsigned ah[4], al[4];
            ah[0] = pksplit(t0[0], t0[1], al[0]);
            ah[1] = pksplit(t0[2], t0[3], al[1]);
            ah[2] = pksplit(t1[0], t1[1], al[2]);
            ah[3] = pksplit(t1[2], t1[3], al[3]);
            #pragma unroll
            for (int ntp = 0; ntp < 4; ntp++) {
                unsigned vh[4], vl[4];
                ldsm4t(vh, &Vsh[(kk*16 + vrow)*KS_STRIDE + ntp*8 + vword]);
                ldsm4t(vl, &Vsl[(kk*16 + vrow)*KS_STRIDE + ntp*8 + vword]);
                mma16816(o[2*ntp],     ah, vh + 0);
                mma16816(o[2*ntp],     ah, vl + 0);
                mma16816(o[2*ntp],     al, vh + 0);
                mma16816(o[2*ntp + 1], ah, vh + 2);
                mma16816(o[2*ntp + 1], ah, vl + 2);
                mma16816(o[2*ntp + 1], al, vh + 2);
            }
        }
        __syncthreads();
    }

    // ---- epilogue: normalize, fmask, split-store merged-head H ----
    const int grow0 = b*CN + qt*128 + wid*16 + qr;
    const int grow1 = grow0 + 8;
    float f0 = fmask[grow0] / l0;
    float f1 = fmask[grow1] / l1;
    #pragma unroll
    for (int nt2 = 0; nt2 < 8; nt2++) {
        int col = h*CHD + nt2*8 + qk*2;
        size_t i0 = (size_t)grow0*CO + col;
        size_t i1 = (size_t)grow1*CO + col;
        unsigned pl0, ph0 = pksplit(o[nt2][0]*f0, o[nt2][1]*f0, pl0);
        unsigned pl1, ph1 = pksplit(o[nt2][2]*f1, o[nt2][3]*f1, pl1);
        *(unsigned*)(Hh + i0) = ph0;
        *(unsigned*)(Hl + i0) = pl0;
        *(unsigned*)(Hh + i1) = ph1;
        *(unsigned*)(Hl + i1) = pl1;
    }
}

// ---------------------------------------------------------------------------
extern "C" void kernel_launch(void* const* d_in, const int* in_sizes, int n_in,
                              void* d_out, int out_size)
{
    const float* x = 0;  const unsigned char* mask_raw = 0;
    const float* slw = 0; const float* qkv_w = 0; const float* qkv_b = 0;
    const float* wbig[3] = {0,0,0}; const float* bsm[3] = {0,0,0};
    int nw = 0, nb = 0;

    for (int i = 0; i < n_in; i++) {
        switch (in_sizes[i]) {
            case 4194304: x        = (const float*)d_in[i]; break;
            case 8388608: /* adj unused */                  break;
            case 8192:    mask_raw = (const unsigned char*)d_in[i]; break;
            case 8:       slw      = (const float*)d_in[i]; break;
            case 786432:  qkv_w    = (const float*)d_in[i]; break;
            case 1536:    qkv_b    = (const float*)d_in[i]; break;
            case 262144:  if (nw < 3) wbig[nw++] = (const float*)d_in[i]; break;
            case 512:     if (nb < 3) bsm[nb++]  = (const float*)d_in[i]; break;
            default: break;
        }
    }
    const float *w1 = wbig[0], *w2 = wbig[1], *wr = wbig[2];
    const float *b1 = bsm[0],  *b2 = bsm[1],  *br = bsm[2];
    float* out = (float*)d_out;

    void *pf, *pxh, *pxl, *pqwh, *pqwl, *pw1h, *pw1l, *pw2h, *pw2l, *pwrh, *pwrl;
    void *pqh, *pql, *pHh, *pHl, *pTh, *pTl;
    cudaGetSymbolAddress(&pf,   g_fmask);
    cudaGetSymbolAddress(&pxh,  g_xh);   cudaGetSymbolAddress(&pxl,  g_xl);
    cudaGetSymbolAddress(&pqwh, g_qwh);  cudaGetSymbolAddress(&pqwl, g_qwl);
    cudaGetSymbolAddress(&pw1h, g_w1h);  cudaGetSymbolAddress(&pw1l, g_w1l);
    cudaGetSymbolAddress(&pw2h, g_w2h);  cudaGetSymbolAddress(&pw2l, g_w2l);
    cudaGetSymbolAddress(&pwrh, g_wrh);  cudaGetSymbolAddress(&pwrl, g_wrl);
    cudaGetSymbolAddress(&pqh,  g_qh);   cudaGetSymbolAddress(&pql,  g_ql);
    cudaGetSymbolAddress(&pHh,  g_Hh);   cudaGetSymbolAddress(&pHl,  g_Hl);
    cudaGetSymbolAddress(&pTh,  g_Th);   cudaGetSymbolAddress(&pTl,  g_Tl);

    float* fmp = (float*)pf;
    __nv_bfloat16 *xh=(__nv_bfloat16*)pxh, *xl=(__nv_bfloat16*)pxl;
    __nv_bfloat16 *qwh=(__nv_bfloat16*)pqwh, *qwl=(__nv_bfloat16*)pqwl;
    __nv_bfloat16 *w1h=(__nv_bfloat16*)pw1h, *w1l=(__nv_bfloat16*)pw1l;
    __nv_bfloat16 *w2h=(__nv_bfloat16*)pw2h, *w2l=(__nv_bfloat16*)pw2l;
    __nv_bfloat16 *wrh=(__nv_bfloat16*)pwrh, *wrl=(__nv_bfloat16*)pwrl;
    __nv_bfloat16 *qhp=(__nv_bfloat16*)pqh, *qlp=(__nv_bfloat16*)pql;
    __nv_bfloat16 *Hhp=(__nv_bfloat16*)pHh, *Hlp=(__nv_bfloat16*)pHl;
    __nv_bfloat16 *Thp=(__nv_bfloat16*)pTh, *Tlp=(__nv_bfloat16*)pTl;

    static int smem_set = 0;
    if (!smem_set) {
        cudaFuncSetAttribute(flash_fat, cudaFuncAttributeMaxDynamicSharedMemorySize,
                             FAT_SMEM);
        cudaFuncSetAttribute(gemm_tc<0>, cudaFuncAttributeMaxDynamicSharedMemorySize,
                             GEMM_SMEM);
        cudaFuncSetAttribute(gemm_tc<1>, cudaFuncAttributeMaxDynamicSharedMemorySize,
                             GEMM_SMEM);
        cudaFuncSetAttribute(gemm_tc<3>, cudaFuncAttributeMaxDynamicSharedMemorySize,
                             GEMM_SMEM);
        smem_set = 1;
    }

    // 0) mask convert + fused one-time splits
    mask_convert<<<1, 256>>>(mask_raw, fmp);
    split5<<<(SPLT+255)/256, 256>>>(x, qkv_w, w1, w2, wr,
                                    xh, xl, qwh, qwl, w1h, w1l, w2h, w2l, wrh, wrl);

    // 1) QKV = x @ qkv_w^T + qkv_b  -> split bf16
    gemm_tc<0><<<dim3(12, 64), 256, GEMM_SMEM>>>(xh, xl, qwh, qwl, qkv_b, fmp,
                                      (float*)0, qhp, qlp, CD, CD, CD, QKVLD);

    // 2-4) flash attention + residual gemm (tail-filled) in one launch
    flash_fat<<<768, 256, FAT_SMEM>>>(qhp, qlp, slw, fmp, Hhp, Hlp,
                                      xh, xl, wrh, wrl, br, out);

    // 5) T = relu(H @ w1^T + b1) -> split bf16
    gemm_tc<1><<<dim3(4, 64), 256, GEMM_SMEM>>>(Hhp, Hlp, w1h, w1l, b1, fmp,
                                     (float*)0, Thp, Tlp, CO, CO, CO, CO);

    // 6) out += 0.5*fmask*(T @ w2^T + b2)   (out initialized by fat kernel)
    gemm_tc<3><<<dim3(4, 64), 256, GEMM_SMEM>>>(Thp, Tlp, w2h, w2l, b2, fmp,
                                     out, (__nv_bfloat16*)0, (__nv_bfloat16*)0, CO, CO, CO, CO);
}

// round 15
// speedup vs baseline: 1.1433x; 1.0131x over previous
#include <cuda_runtime.h>
#include <cuda_bf16.h>
#include <math.h>

// Problem constants
#define CB 8
#define CN 1024
#define CD 512
#define CO 512
#define CH 8
#define CHD 64
#define QKVLD 1536   // 3*O
#define MROWS (CB*CN) // 8192

// ---------------- scratch (static device allocations; no cudaMalloc) ----------
__device__ float g_fmask[MROWS];
__device__ int   g_qcnt[CB];      // qkv completion per batch (96 tiles each)
__device__ int   g_tcnt[64];      // FFN1 completion per 128-row block (4 tiles each)
__device__ __nv_bfloat16 g_xh[MROWS*CD],  g_xl[MROWS*CD];
__device__ __nv_bfloat16 g_qwh[QKVLD*CD], g_qwl[QKVLD*CD];
__device__ __nv_bfloat16 g_w1h[CO*CO], g_w1l[CO*CO];
__device__ __nv_bfloat16 g_w2h[CO*CO], g_w2l[CO*CO];
__device__ __nv_bfloat16 g_wrh[CO*CD], g_wrl[CO*CD];
__device__ __nv_bfloat16 g_qh[(size_t)MROWS*QKVLD], g_ql[(size_t)MROWS*QKVLD];
__device__ __nv_bfloat16 g_Hh[MROWS*CO], g_Hl[MROWS*CO];
__device__ __nv_bfloat16 g_Th[MROWS*CO], g_Tl[MROWS*CO];

// ---------------------------------------------------------------------------
__device__ __forceinline__ void bsplit(float v, __nv_bfloat16& h, __nv_bfloat16& l){
    h = __float2bfloat16(v);
    l = __float2bfloat16(v - __bfloat162float(h));
}
// Packed split: hi = bf16x2(v0,v1), lo = bf16x2 residuals (RN, bit-identical).
__device__ __forceinline__ unsigned pksplit(float v0, float v1, unsigned& lo){
    unsigned hi;
    asm("cvt.rn.bf16x2.f32 %0, %1, %2;" : "=r"(hi) : "f"(v1), "f"(v0));
    float h0 = __uint_as_float(hi << 16);
    float h1 = __uint_as_float(hi & 0xffff0000u);
    asm("cvt.rn.bf16x2.f32 %0, %1, %2;" : "=r"(lo) : "f"(v1 - h1), "f"(v0 - h0));
    return hi;
}
__device__ __forceinline__ void mma16816(float* c, const unsigned* a, const unsigned* b){
    asm volatile("mma.sync.aligned.m16n8k16.row.col.f32.bf16.bf16.f32 "
        "{%0,%1,%2,%3}, {%4,%5,%6,%7}, {%8,%9}, {%0,%1,%2,%3};"
        : "+f"(c[0]), "+f"(c[1]), "+f"(c[2]), "+f"(c[3])
        : "r"(a[0]), "r"(a[1]), "r"(a[2]), "r"(a[3]), "r"(b[0]), "r"(b[1]));
}
__device__ __forceinline__ void ldsm4(unsigned* r, const void* p){
    unsigned a = (unsigned)__cvta_generic_to_shared(p);
    asm volatile("ldmatrix.sync.aligned.m8n8.x4.shared.b16 {%0,%1,%2,%3}, [%4];"
        : "=r"(r[0]), "=r"(r[1]), "=r"(r[2]), "=r"(r[3]) : "r"(a));
}
__device__ __forceinline__ void ldsm4t(unsigned* r, const void* p){
    unsigned a = (unsigned)__cvta_generic_to_shared(p);
    asm volatile("ldmatrix.sync.aligned.m8n8.x4.trans.shared.b16 {%0,%1,%2,%3}, [%4];"
        : "=r"(r[0]), "=r"(r[1]), "=r"(r[2]), "=r"(r[3]) : "r"(a));
}
__device__ __forceinline__ void ldsm2(unsigned* r, const void* p){
    unsigned a = (unsigned)__cvta_generic_to_shared(p);
    asm volatile("ldmatrix.sync.aligned.m8n8.x2.shared.b16 {%0,%1}, [%2];"
        : "=r"(r[0]), "=r"(r[1]) : "r"(a));
}
__device__ __forceinline__ void cpa16(void* dst_smem, const void* src){
    unsigned sa = (unsigned)__cvta_generic_to_shared(dst_smem);
    asm volatile("cp.async.cg.shared.global [%0], [%1], 16;" :: "r"(sa), "l"(src));
}
#define CPA_COMMIT asm volatile("cp.async.commit_group;")
#define CPA_WAIT0  asm volatile("cp.async.wait_group 0;")

// producer publish: all threads fence, then one increments the counter
__device__ __forceinline__ void publish(int* cnt){
    __threadfence();
    __syncthreads();
    if (threadIdx.x == 0) atomicAdd(cnt, 1);
}
// consumer wait: thread 0 spins until counter reaches need
__device__ __forceinline__ void await(int* cnt, int need){
    if (threadIdx.x == 0) {
        while (atomicAdd(cnt, 0) < need) __nanosleep(128);
    }
    __syncthreads();
    __threadfence();
}

// ---------------------------------------------------------------------------
// Mask conversion (dtype auto-detect; bench data treated strictly as data)
// + zero the dependency counters for this call (graph-replay safe).
// ---------------------------------------------------------------------------
__global__ void mask_convert(const unsigned char* __restrict__ raw,
                             float* __restrict__ fmask,
                             int* __restrict__ qcnt, int* __restrict__ tcnt)
{
    __shared__ int s_m1, s_m23, s_gt1;
    int t = threadIdx.x;
    if (t < CB) qcnt[t] = 0;
    if (t < 64) tcnt[t] = 0;
    if (t == 0) { s_m1 = 0; s_m23 = 0; s_gt1 = 0; }
    __syncthreads();
    int m1 = 0, m23 = 0, g = 0;
    for (int i = t; i < MROWS; i += 256) {
        unsigned char v = raw[i];
        if (v) {
            int p = i & 3;
            if (p == 1) m1 = 1;
            if (p >= 2) m23 = 1;
            if (v > 1) g = 1;
        }
    }
    if (m1)  atomicOr(&s_m1, 1);
    if (m23) atomicOr(&s_m23, 1);
    if (g)   atomicOr(&s_gt1, 1);
    __syncthreads();
    int mis = s_m1 | s_m23;
    int mode;
    if (!mis)            mode = 0;
    else if (!s_gt1)     mode = 1;
    else if (s_m1)       mode = 3;
    else                 mode = 2;
    for (int i = t; i < MROWS; i += 256) {
        float f;
        if (mode == 0)      f = (((const int*)raw)[i]            != 0)   ? 1.f : 0.f;
        else if (mode == 1) f = (raw[i]                          != 0)   ? 1.f : 0.f;
        else if (mode == 2) f = (((const float*)raw)[i]          != 0.f) ? 1.f : 0.f;
        else                f = (((const unsigned short*)raw)[i] != 0)   ? 1.f : 0.f;
        fmask[i] = f;
    }
}

// ---------------------------------------------------------------------------
// Fused splitter: x, qkv_w, w1, w2, wr in one launch.
// ---------------------------------------------------------------------------
#define SPL0 (MROWS*CD)
#define SPL1 (QKVLD*CD)
#define SPL2 (CO*CO)
#define SPL3 (CO*CO)
#define SPL4 (CO*CD)
#define SPLT (SPL0+SPL1+SPL2+SPL3+SPL4)
__global__ void split5(
    const float* __restrict__ s0, const float* __restrict__ s1,
    const float* __restrict__ s2, const float* __restrict__ s3,
    const float* __restrict__ s4,
    __nv_bfloat16* __restrict__ h0, __nv_bfloat16* __restrict__ l0,
    __nv_bfloat16* __restrict__ h1, __nv_bfloat16* __restrict__ l1,
    __nv_bfloat16* __restrict__ h2, __nv_bfloat16* __restrict__ l2,
    __nv_bfloat16* __restrict__ h3, __nv_bfloat16* __restrict__ l3,
    __nv_bfloat16* __restrict__ h4, __nv_bfloat16* __restrict__ l4)
{
    int i = blockIdx.x * 256 + threadIdx.x;
    if (i >= SPLT) return;
    const float* s; __nv_bfloat16 *h, *l; int j = i;
    if (j < SPL0)                { s = s0; h = h0; l = l0; }
    else if ((j -= SPL0) < SPL1) { s = s1; h = h1; l = l1; }
    else if ((j -= SPL1) < SPL2) { s = s2; h = h2; l = l2; }
    else if ((j -= SPL2) < SPL3) { s = s3; h = h3; l = l3; }
    else { j -= SPL3;              s = s4; h = h4; l = l4; }
    __nv_bfloat16 hh, ll;
    bsplit(s[j], hh, ll);
    h[j] = hh; l[j] = ll;
}

// ---------------------------------------------------------------------------
// HMMA NT GEMM body (bf16x3), BK=32, cp.async double-buffered, ldmatrix.
// Dynamic smem: Ah[2][2560] | Al | Wh | Wl = 81920 B, row stride 20 u32.
// 128x128 tile, 256 thr (8 warps = 2m x 4n).
// EPI: 0 split-store; 1 relu+split-store; 2 Cf=0.5v; 3 Cf+=0.5*fmask[m]*v
// ---------------------------------------------------------------------------
#define GW 20
#define GSTG (128*GW)
#define GEMM_SMEM (8*GSTG*4)  // 81920

template<int EPI>
__device__ __forceinline__ void gemm_body(
    unsigned* sm, int bx, int by,
    const __nv_bfloat16* __restrict__ Ahg, const __nv_bfloat16* __restrict__ Alg,
    const __nv_bfloat16* __restrict__ Whg, const __nv_bfloat16* __restrict__ Wlg,
    const float* __restrict__ bias, const float* __restrict__ fmask,
    float* __restrict__ Cf, __nv_bfloat16* __restrict__ Ch, __nv_bfloat16* __restrict__ Cl,
    int K, int lda, int ldw, int ldc)
{
    unsigned* Ah = sm;
    unsigned* Al = sm + 2*GSTG;
    unsigned* Wh = sm + 4*GSTG;
    unsigned* Wl = sm + 6*GSTG;
    const int tid = threadIdx.x;
    const int lane = tid & 31, wid = tid >> 5;
    const int wm = wid & 1, wn = wid >> 1;
    const int row0 = by * 128, col0 = bx * 128;
    const int lr = tid >> 1, lq = tid & 1;
    const int qr = lane >> 2, qk = lane & 3;

    const int arow  = wm*64 + (lane & 7) + ((lane >> 3) & 1) * 8;
    const int aword = ((lane >> 4) & 1) * 4;
    const int brow  = wn*32 + (lane & 7);
    const int bword = ((lane >> 3) & 1) * 4;

    float acc[4][4][4];
    #pragma unroll
    for (int mt = 0; mt < 4; mt++)
        #pragma unroll
        for (int nt = 0; nt < 4; nt++)
            #pragma unroll
            for (int i = 0; i < 4; i++) acc[mt][nt][i] = 0.f;

    {
        size_t aoff = (size_t)(row0 + lr) * lda + lq * 16;
        size_t woff = (size_t)(col0 + lr) * ldw + lq * 16;
        #pragma unroll
        for (int j = 0; j < 2; j++) {
            cpa16(&Ah[lr*GW + lq*8 + j*4], Ahg + aoff + j*8);
            cpa16(&Al[lr*GW + lq*8 + j*4], Alg + aoff + j*8);
            cpa16(&Wh[lr*GW + lq*8 + j*4], Whg + woff + j*8);
            cpa16(&Wl[lr*GW + lq*8 + j*4], Wlg + woff + j*8);
        }
    }
    CPA_COMMIT;

    int st = 0;
    for (int k0 = 0; k0 < K; k0 += 32, st ^= 1) {
        CPA_WAIT0;
        __syncthreads();
        if (k0 + 32 < K) {
            const int so = (st^1) * GSTG;
            size_t aoff = (size_t)(row0 + lr) * lda + k0 + 32 + lq * 16;
            size_t woff = (size_t)(col0 + lr) * ldw + k0 + 32 + lq * 16;
            #pragma unroll
            for (int j = 0; j < 2; j++) {
                cpa16(&Ah[so + lr*GW + lq*8 + j*4], Ahg + aoff + j*8);
                cpa16(&Al[so + lr*GW + lq*8 + j*4], Alg + aoff + j*8);
                cpa16(&Wh[so + lr*GW + lq*8 + j*4], Whg + woff + j*8);
                cpa16(&Wl[so + lr*GW + lq*8 + j*4], Wlg + woff + j*8);
            }
        }
        CPA_COMMIT;

        const int sc = st * GSTG;
        #pragma unroll
        for (int g = 0; g < 2; g++) {
            unsigned afh[4][4], afl[4][4], bfh[4][2], bfl[4][2];
            #pragma unroll
            for (int mt = 0; mt < 4; mt++) {
                ldsm4(afh[mt], &Ah[sc + (arow + mt*16)*GW + g*8 + aword]);
                ldsm4(afl[mt], &Al[sc + (arow + mt*16)*GW + g*8 + aword]);
            }
            #pragma unroll
            for (int nt = 0; nt < 4; nt++) {
                ldsm2(bfh[nt], &Wh[sc + (brow + nt*8)*GW + g*8 + bword]);
                ldsm2(bfl[nt], &Wl[sc + (brow + nt*8)*GW + g*8 + bword]);
            }
            #pragma unroll
            for (int mt = 0; mt < 4; mt++)
                #pragma unroll
                for (int nt = 0; nt < 4; nt++) {
                    mma16816(acc[mt][nt], afh[mt], bfh[nt]);
                    mma16816(acc[mt][nt], afh[mt], bfl[nt]);
                    mma16816(acc[mt][nt], afl[mt], bfh[nt]);
                }
        }
    }

    #pragma unroll
    for (int mt = 0; mt < 4; mt++)
        #pragma unroll
        for (int nt = 0; nt < 4; nt++) {
            const float* a = acc[mt][nt];
            int rbase = row0 + wm*64 + mt*16 + qr;
            int cbase = col0 + wn*32 + nt*8 + qk*2;
            float bv0 = bias[cbase], bv1 = bias[cbase + 1];
            #pragma unroll
            for (int hf = 0; hf < 2; hf++) {
                int r = rbase + hf*8;
                float v0 = a[hf*2+0] + bv0;
                float v1 = a[hf*2+1] + bv1;
                size_t idx = (size_t)r * ldc + cbase;
                if constexpr (EPI == 0 || EPI == 1) {
                    if constexpr (EPI == 1) { v0 = fmaxf(v0, 0.f); v1 = fmaxf(v1, 0.f); }
                    unsigned pl, ph = pksplit(v0, v1, pl);
                    *(unsigned*)(Ch + idx) = ph;
                    *(unsigned*)(Cl + idx) = pl;
                } else if constexpr (EPI == 2) {
                    float2 o; o.x = 0.5f*v0; o.y = 0.5f*v1;
                    *(float2*)(Cf + idx) = o;
                } else {
                    float fm = 0.5f * fmask[r];
                    float2 cur = *(float2*)(Cf + idx);
                    cur.x += fm*v0; cur.y += fm*v1;
                    *(float2*)(Cf + idx) = cur;
                }
            }
        }
}

// ---------------------------------------------------------------------------
// Flash body (R13 form: single-buffer K/V, V row-major + ldsm4t, pksplit).
// ---------------------------------------------------------------------------
#define KS_STRIDE 36
#define KS_WORDS (128*KS_STRIDE)
#define FAT_SMEM (GEMM_SMEM)             // 81920 >= flash's 73728

__device__ __forceinline__ void flash_body(
    unsigned* smem, int qt, int b, int h,
    const __nv_bfloat16* __restrict__ qh, const __nv_bfloat16* __restrict__ ql,
    const float* __restrict__ slw, const float* __restrict__ fmask,
    __nv_bfloat16* __restrict__ Hh, __nv_bfloat16* __restrict__ Hl)
{
    unsigned* Ksh = smem;
    unsigned* Ksl = smem + KS_WORDS;
    unsigned* Vsh = smem + 2*KS_WORDS;
    unsigned* Vsl = smem + 3*KS_WORDS;

    const int tid = threadIdx.x;
    const int lane = tid & 31, wid = tid >> 5;
    const int qr = lane >> 2, qk = lane & 3;

    const size_t bhq = (size_t)b*CN*QKVLD + h*CHD;
    const size_t bhk = bhq + CO;
    const size_t bhv = bhq + 2*CO;

    const int lrow = tid >> 1, lq = tid & 1;
    const int krow  = ((lane >> 4) & 1) * 8 + (lane & 7);
    const int kword = ((lane >> 3) & 1) * 4;
    const int vrow  = lane & 15;
    const int vword = (lane >> 4) * 4;

    {
        size_t qoff = bhq + (size_t)(qt*128 + lrow)*QKVLD + lq*32;
        #pragma unroll
        for (int i = 0; i < 4; i++) {
            *(uint4*)&Ksh[lrow*KS_STRIDE + lq*16 + i*4] = *(const uint4*)(qh + qoff + i*8);
            *(uint4*)&Ksl[lrow*KS_STRIDE + lq*16 + i*4] = *(const uint4*)(ql + qoff + i*8);
        }
    }
    __syncthreads();
    unsigned qfh[4][4], qfl[4][4];
    #pragma unroll
    for (int kw = 0; kw < 4; kw++) {
        int r0 = (wid*16 + qr) * KS_STRIDE + kw*8;
        int r8 = (wid*16 + qr + 8) * KS_STRIDE + kw*8;
        qfh[kw][0] = Ksh[r0 + qk];     qfh[kw][1] = Ksh[r8 + qk];
        qfh[kw][2] = Ksh[r0 + qk + 4]; qfh[kw][3] = Ksh[r8 + qk + 4];
        qfl[kw][0] = Ksl[r0 + qk];     qfl[kw][1] = Ksl[r8 + qk];
        qfl[kw][2] = Ksl[r0 + qk + 4]; qfl[kw][3] = Ksl[r8 + qk + 4];
    }
    __syncthreads();

    const float wd = slw[h];
    float o[8][4];
    #pragma unroll
    for (int i = 0; i < 8; i++)
        #pragma unroll
        for (int j = 0; j < 4; j++) o[i][j] = 0.f;
    float m0 = -1e30f, m1 = -1e30f, l0 = 0.f, l1 = 0.f;

    for (int kt = 0; kt < 8; kt++) {
        {
            size_t koff = bhk + (size_t)(kt*128 + lrow)*QKVLD + lq*32;
            size_t voff = bhv + (size_t)(kt*128 + lrow)*QKVLD + lq*32;
            #pragma unroll
            for (int i = 0; i < 4; i++) {
                *(uint4*)&Ksh[lrow*KS_STRIDE + lq*16 + i*4] = *(const uint4*)(qh + koff + i*8);
                *(uint4*)&Ksl[lrow*KS_STRIDE + lq*16 + i*4] = *(const uint4*)(ql + koff + i*8);
                *(uint4*)&Vsh[lrow*KS_STRIDE + lq*16 + i*4] = *(const uint4*)(qh + voff + i*8);
                *(uint4*)&Vsl[lrow*KS_STRIDE + lq*16 + i*4] = *(const uint4*)(ql + voff + i*8);
            }
        }
        __syncthreads();

        const float* fmc = fmask + b*CN + kt*128;

        float s[16][4];
        #pragma unroll
        for (int nt = 0; nt < 16; nt++)
            #pragma unroll
            for (int i = 0; i < 4; i++) s[nt][i] = 0.f;
        #pragma unroll
        for (int ntp = 0; ntp < 8; ntp++) {
            float* sA = s[2*ntp];
            float* sB = s[2*ntp + 1];
            #pragma unroll
            for (int kw = 0; kw < 4; kw++) {
                unsigned kh[4], kl[4];
                ldsm4(kh, &Ksh[(ntp*16 + krow)*KS_STRIDE + kw*8 + kword]);
                ldsm4(kl, &Ksl[(ntp*16 + krow)*KS_STRIDE + kw*8 + kword]);
                mma16816(sA, qfh[kw], kh + 0);
                mma16816(sA, qfh[kw], kl + 0);
                mma16816(sA, qfl[kw], kh + 0);
                mma16816(sB, qfh[kw], kh + 2);
                mma16816(sB, qfh[kw], kl + 2);
                mma16816(sB, qfl[kw], kh + 2);
            }
        }

        const int lr0 = wid*16 + qr, lr1 = lr0 + 8;
        float tmax0 = -3e38f, tmax1 = -3e38f;
        #pragma unroll
        for (int nt = 0; nt < 16; nt++) {
            int c0 = nt*8 + qk*2;
            float2 cmv = *(const float2*)(fmc + c0);
            float v0 = s[nt][0]*0.125f, v1 = s[nt][1]*0.125f;
            float v2 = s[nt][2]*0.125f, v3 = s[nt][3]*0.125f;
            if (qt == kt) {
                if (lr0 == c0)     v0 += wd;
                if (lr0 == c0 + 1) v1 += wd;
                if (lr1 == c0)     v2 += wd;
                if (lr1 == c0 + 1) v3 += wd;
            }
            if (cmv.x == 0.f) { v0 = -1e6f; v2 = -1e6f; }
            if (cmv.y == 0.f) { v1 = -1e6f; v3 = -1e6f; }
            s[nt][0] = v0; s[nt][1] = v1; s[nt][2] = v2; s[nt][3] = v3;
            tmax0 = fmaxf(tmax0, fmaxf(v0, v1));
            tmax1 = fmaxf(tmax1, fmaxf(v2, v3));
        }
        #pragma unroll
        for (int off = 1; off <= 2; off <<= 1) {
            tmax0 = fmaxf(tmax0, __shfl_xor_sync(0xffffffffu, tmax0, off));
            tmax1 = fmaxf(tmax1, __shfl_xor_sync(0xffffffffu, tmax1, off));
        }
        float mn0 = fmaxf(m0, tmax0), mn1 = fmaxf(m1, tmax1);
        float sc0 = __expf(m0 - mn0), sc1 = __expf(m1 - mn1);
        m0 = mn0; m1 = mn1;
        l0 *= sc0; l1 *= sc1;
        #pragma unroll
        for (int nt2 = 0; nt2 < 8; nt2++) {
            o[nt2][0] *= sc0; o[nt2][1] *= sc0;
            o[nt2][2] *= sc1; o[nt2][3] *= sc1;
        }
        float rs0 = 0.f, rs1 = 0.f;
        #pragma unroll
        for (int nt = 0; nt < 16; nt++) {
            float p0 = __expf(s[nt][0] - mn0);
            float p1 = __expf(s[nt][1] - mn0);
            float p2 = __expf(s[nt][2] - mn1);
            float p3 = __expf(s[nt][3] - mn1);
            rs0 += p0 + p1; rs1 += p2 + p3;
            s[nt][0] = p0; s[nt][1] = p1; s[nt][2] = p2; s[nt][3] = p3;
        }
        #pragma unroll
        for (int off = 1; off <= 2; off <<= 1) {
            rs0 += __shfl_xor_sync(0xffffffffu, rs0, off);
            rs1 += __shfl_xor_sync(0xffffffffu, rs1, off);
        }
        l0 += rs0; l1 += rs1;

        #pragma unroll
        for (int kk = 0; kk < 8; kk++) {
            const float* t0 = s[2*kk];
            const float* t1 = s[2*kk + 1];
            unsigned ah[4], al[4];
            ah[0] = pksplit(t0[0], t0[1], al[0]);
            ah[1] = pksplit(t0[2], t0[3], al[1]);
            ah[2] = pksplit(t1[0], t1[1], al[2]);
            ah[3] = pksplit(t1[2], t1[3], al[3]);
            #pragma unroll
            for (int ntp = 0; ntp < 4; ntp++) {
                unsigned vh[4], vl[4];
                ldsm4t(vh, &Vsh[(kk*16 + vrow)*KS_STRIDE + ntp*8 + vword]);
                ldsm4t(vl, &Vsl[(kk*16 + vrow)*KS_STRIDE + ntp*8 + vword]);
                mma16816(o[2*ntp],     ah, vh + 0);
                mma16816(o[2*ntp],     ah, vl + 0);
                mma16816(o[2*ntp],     al, vh + 0);
                mma16816(o[2*ntp + 1], ah, vh + 2);
                mma16816(o[2*ntp + 1], ah, vl + 2);
                mma16816(o[2*ntp + 1], al, vh + 2);
            }
        }
        __syncthreads();
    }

    const int grow0 = b*CN + qt*128 + wid*16 + qr;
    const int grow1 = grow0 + 8;
    float f0 = fmask[grow0] / l0;
    float f1 = fmask[grow1] / l1;
    #pragma unroll
    for (int nt2 = 0; nt2 < 8; nt2++) {
        int col = h*CHD + nt2*8 + qk*2;
        size_t i0 = (size_t)grow0*CO + col;
        size_t i1 = (size_t)grow1*CO + col;
        unsigned pl0, ph0 = pksplit(o[nt2][0]*f0, o[nt2][1]*f0, pl0);
        unsigned pl1, ph1 = pksplit(o[nt2][2]*f1, o[nt2][3]*f1, pl1);
        *(unsigned*)(Hh + i0) = ph0;
        *(unsigned*)(Hl + i0) = pl0;
        *(unsigned*)(Hh + i1) = ph1;
        *(unsigned*)(Hl + i1) = pl1;
    }
}

// ---------------------------------------------------------------------------
// MEGA kernel (1536 blocks): qkv GEMM tiles + flash tiles + residual tiles,
// interleaved per batch with spin-fence dependencies.
// bid layout: [qkv b0 (96)] then for g=0..6: [qkv b(g+1) (96)][flash bg (64)]
// then [flash b7 (64)] then [residual (256)].
// ---------------------------------------------------------------------------
__global__ void __launch_bounds__(256, 1) mega(
    const __nv_bfloat16* __restrict__ xh, const __nv_bfloat16* __restrict__ xl,
    const __nv_bfloat16* __restrict__ qwh, const __nv_bfloat16* __restrict__ qwl,
    const float* __restrict__ qkv_b,
    __nv_bfloat16* __restrict__ qh, __nv_bfloat16* __restrict__ ql,
    const float* __restrict__ slw, const float* __restrict__ fmask,
    __nv_bfloat16* __restrict__ Hh, __nv_bfloat16* __restrict__ Hl,
    const __nv_bfloat16* __restrict__ wrh, const __nv_bfloat16* __restrict__ wrl,
    const float* __restrict__ br, float* __restrict__ out,
    int* __restrict__ qcnt)
{
    extern __shared__ unsigned smem[];
    const int bid = blockIdx.x;

    int kind, batch, sub;   // kind 0=qkv 1=flash 2=residual
    if (bid < 96)            { kind = 0; batch = 0; sub = bid; }
    else if (bid < 1216) {
        int t = bid - 96, g = t / 160, r = t % 160;
        if (r < 96)          { kind = 0; batch = g + 1; sub = r; }
        else                 { kind = 1; batch = g;     sub = r - 96; }
    }
    else if (bid < 1280)     { kind = 1; batch = 7; sub = bid - 1216; }
    else                     { kind = 2; batch = 0; sub = bid - 1280; }

    if (kind == 0) {
        // qkv tile: rows = batch*1024 + (sub/12)*128, cols = (sub%12)*128
        int by = batch * 8 + sub / 12;
        int bx = sub % 12;
        gemm_body<0>(smem, bx, by, xh, xl, qwh, qwl, qkv_b, fmask,
                     (float*)0, qh, ql, CD, CD, CD, QKVLD);
        publish(&qcnt[batch]);
    } else if (kind == 1) {
        await(&qcnt[batch], 96);
        int h = sub >> 3, qt = sub & 7;
        flash_body(smem, qt, batch, h, qh, ql, slw, fmask, Hh, Hl);
    } else {
        gemm_body<2>(smem, sub & 3, sub >> 2, xh, xl, wrh, wrl, br, fmask,
                     out, (__nv_bfloat16*)0, (__nv_bfloat16*)0, CD, CD, CD, CO);
    }
}

// ---------------------------------------------------------------------------
// FFN kernel (512 blocks): FFN1 tiles (0..255) publish per-row-block counters;
// FFN2 tiles (256..511) spin on their 4 producer tiles then accumulate out.
// ---------------------------------------------------------------------------
__global__ void __launch_bounds__(256, 1) ffn_fused(
    const __nv_bfloat16* __restrict__ Hh, const __nv_bfloat16* __restrict__ Hl,
    const __nv_bfloat16* __restrict__ w1h, const __nv_bfloat16* __restrict__ w1l,
    const float* __restrict__ b1,
    __nv_bfloat16* __restrict__ Th, __nv_bfloat16* __restrict__ Tl,
    const __nv_bfloat16* __restrict__ w2h, const __nv_bfloat16* __restrict__ w2l,
    const float* __restrict__ b2,
    const float* __restrict__ fmask, float* __restrict__ out,
    int* __restrict__ tcnt)
{
    extern __shared__ unsigned smem[];
    const int bid = blockIdx.x;
    if (bid < 256) {
        int by = bid >> 2, bx = bid & 3;
        gemm_body<1>(smem, bx, by, Hh, Hl, w1h, w1l, b1, fmask,
                     (float*)0, Th, Tl, CO, CO, CO, CO);
        publish(&tcnt[by]);
    } else {
        int j = bid - 256;
        int by = j >> 2, bx = j & 3;
        await(&tcnt[by], 4);
        gemm_body<3>(smem, bx, by, Th, Tl, w2h, w2l, b2, fmask,
                     out, (__nv_bfloat16*)0, (__nv_bfloat16*)0, CO, CO, CO, CO);
    }
}

// ---------------------------------------------------------------------------
extern "C" void kernel_launch(void* const* d_in, const int* in_sizes, int n_in,
                              void* d_out, int out_size)
{
    const float* x = 0;  const unsigned char* mask_raw = 0;
    const float* slw = 0; const float* qkv_w = 0; const float* qkv_b = 0;
    const float* wbig[3] = {0,0,0}; const float* bsm[3] = {0,0,0};
    int nw = 0, nb = 0;

    for (int i = 0; i < n_in; i++) {
        switch (in_sizes[i]) {
            case 4194304: x        = (const float*)d_in[i]; break;
            case 8388608: /* adj unused */                  break;
            case 8192:    mask_raw = (const unsigned char*)d_in[i]; break;
            case 8:       slw      = (const float*)d_in[i]; break;
            case 786432:  qkv_w    = (const float*)d_in[i]; break;
            case 1536:    qkv_b    = (const float*)d_in[i]; break;
            case 262144:  if (nw < 3) wbig[nw++] = (const float*)d_in[i]; break;
            case 512:     if (nb < 3) bsm[nb++]  = (const float*)d_in[i]; break;
            default: break;
        }
    }
    const float *w1 = wbig[0], *w2 = wbig[1], *wr = wbig[2];
    const float *b1 = bsm[0],  *b2 = bsm[1],  *br = bsm[2];
    float* out = (float*)d_out;

    void *pf, *pqc, *ptc, *pxh, *pxl, *pqwh, *pqwl, *pw1h, *pw1l, *pw2h, *pw2l;
    void *pwrh, *pwrl, *pqh, *pql, *pHh, *pHl, *pTh, *pTl;
    cudaGetSymbolAddress(&pf,   g_fmask);
    cudaGetSymbolAddress(&pqc,  g_qcnt);
    cudaGetSymbolAddress(&ptc,  g_tcnt);
    cudaGetSymbolAddress(&pxh,  g_xh);   cudaGetSymbolAddress(&pxl,  g_xl);
    cudaGetSymbolAddress(&pqwh, g_qwh);  cudaGetSymbolAddress(&pqwl, g_qwl);
    cudaGetSymbolAddress(&pw1h, g_w1h);  cudaGetSymbolAddress(&pw1l, g_w1l);
    cudaGetSymbolAddress(&pw2h, g_w2h);  cudaGetSymbolAddress(&pw2l, g_w2l);
    cudaGetSymbolAddress(&pwrh, g_wrh);  cudaGetSymbolAddress(&pwrl, g_wrl);
    cudaGetSymbolAddress(&pqh,  g_qh);   cudaGetSymbolAddress(&pql,  g_ql);
    cudaGetSymbolAddress(&pHh,  g_Hh);   cudaGetSymbolAddress(&pHl,  g_Hl);
    cudaGetSymbolAddress(&pTh,  g_Th);   cudaGetSymbolAddress(&pTl,  g_Tl);

    float* fmp = (float*)pf;
    int *qcnt = (int*)pqc, *tcnt = (int*)ptc;
    __nv_bfloat16 *xh=(__nv_bfloat16*)pxh, *xl=(__nv_bfloat16*)pxl;
    __nv_bfloat16 *qwh=(__nv_bfloat16*)pqwh, *qwl=(__nv_bfloat16*)pqwl;
    __nv_bfloat16 *w1h=(__nv_bfloat16*)pw1h, *w1l=(__nv_bfloat16*)pw1l;
    __nv_bfloat16 *w2h=(__nv_bfloat16*)pw2h, *w2l=(__nv_bfloat16*)pw2l;
    __nv_bfloat16 *wrh=(__nv_bfloat16*)pwrh, *wrl=(__nv_bfloat16*)pwrl;
    __nv_bfloat16 *qhp=(__nv_bfloat16*)pqh, *qlp=(__nv_bfloat16*)pql;
    __nv_bfloat16 *Hhp=(__nv_bfloat16*)pHh, *Hlp=(__nv_bfloat16*)pHl;
    __nv_bfloat16 *Thp=(__nv_bfloat16*)pTh, *Tlp=(__nv_bfloat16*)pTl;

    static int smem_set = 0;
    if (!smem_set) {
        cudaFuncSetAttribute(mega, cudaFuncAttributeMaxDynamicSharedMemorySize,
                             FAT_SMEM);
        cudaFuncSetAttribute(ffn_fused, cudaFuncAttributeMaxDynamicSharedMemorySize,
                             GEMM_SMEM);
        smem_set = 1;
    }

    // 0) mask convert + counter reset, fused one-time splits
    mask_convert<<<1, 256>>>(mask_raw, fmp, qcnt, tcnt);
    split5<<<(SPLT+255)/256, 256>>>(x, qkv_w, w1, w2, wr,
                                    xh, xl, qwh, qwl, w1h, w1l, w2h, w2l, wrh, wrl);

    // 1) qkv + flash + residual in ONE launch (spin-fenced pipelining)
    mega<<<1536, 256, FAT_SMEM>>>(xh, xl, qwh, qwl, qkv_b, qhp, qlp,
                                  slw, fmp, Hhp, Hlp, wrh, wrl, br, out, qcnt);

    // 2) FFN1 + FFN2 in ONE launch (spin-fenced)
    ffn_fused<<<512, 256, GEMM_SMEM>>>(Hhp, Hlp, w1h, w1l, b1, Thp, Tlp,
                                       w2h, w2l, b2, fmp, out, tcnt);
}

// round 16
// speedup vs baseline: 1.1877x; 1.0388x over previous
#include <cuda_runtime.h>
#include <cuda_bf16.h>
#include <math.h>

// Problem constants
#define CB 8
#define CN 1024
#define CD 512
#define CO 512
#define CH 8
#define CHD 64
#define QKVLD 1536   // 3*O
#define MROWS (CB*CN) // 8192

// ---------------- scratch (static device allocations; no cudaMalloc) ----------
__device__ float g_fmask[MROWS];
__device__ int   g_qcnt[CB];      // qkv completion per batch (96 tiles each)
__device__ int   g_tcnt[64];      // FFN1 completion per 128-row block (4 tiles each)
__device__ __nv_bfloat16 g_xh[MROWS*CD],  g_xl[MROWS*CD];
__device__ __nv_bfloat16 g_qwh[QKVLD*CD], g_qwl[QKVLD*CD];
__device__ __nv_bfloat16 g_w1h[CO*CO], g_w1l[CO*CO];
__device__ __nv_bfloat16 g_w2h[CO*CO], g_w2l[CO*CO];
__device__ __nv_bfloat16 g_wrh[CO*CD], g_wrl[CO*CD];
__device__ __nv_bfloat16 g_qh[(size_t)MROWS*QKVLD], g_ql[(size_t)MROWS*QKVLD];
__device__ __nv_bfloat16 g_Hh[MROWS*CO], g_Hl[MROWS*CO];
__device__ __nv_bfloat16 g_Th[MROWS*CO], g_Tl[MROWS*CO];

// ---------------------------------------------------------------------------
__device__ __forceinline__ void bsplit(float v, __nv_bfloat16& h, __nv_bfloat16& l){
    h = __float2bfloat16(v);
    l = __float2bfloat16(v - __bfloat162float(h));
}
// Packed split: hi = bf16x2(v0,v1), lo = bf16x2 residuals (RN, bit-identical).
__device__ __forceinline__ unsigned pksplit(float v0, float v1, unsigned& lo){
    unsigned hi;
    asm("cvt.rn.bf16x2.f32 %0, %1, %2;" : "=r"(hi) : "f"(v1), "f"(v0));
    float h0 = __uint_as_float(hi << 16);
    float h1 = __uint_as_float(hi & 0xffff0000u);
    asm("cvt.rn.bf16x2.f32 %0, %1, %2;" : "=r"(lo) : "f"(v1 - h1), "f"(v0 - h0));
    return hi;
}
__device__ __forceinline__ void mma16816(float* c, const unsigned* a, const unsigned* b){
    asm volatile("mma.sync.aligned.m16n8k16.row.col.f32.bf16.bf16.f32 "
        "{%0,%1,%2,%3}, {%4,%5,%6,%7}, {%8,%9}, {%0,%1,%2,%3};"
        : "+f"(c[0]), "+f"(c[1]), "+f"(c[2]), "+f"(c[3])
        : "r"(a[0]), "r"(a[1]), "r"(a[2]), "r"(a[3]), "r"(b[0]), "r"(b[1]));
}
__device__ __forceinline__ void ldsm4(unsigned* r, const void* p){
    unsigned a = (unsigned)__cvta_generic_to_shared(p);
    asm volatile("ldmatrix.sync.aligned.m8n8.x4.shared.b16 {%0,%1,%2,%3}, [%4];"
        : "=r"(r[0]), "=r"(r[1]), "=r"(r[2]), "=r"(r[3]) : "r"(a));
}
__device__ __forceinline__ void ldsm4t(unsigned* r, const void* p){
    unsigned a = (unsigned)__cvta_generic_to_shared(p);
    asm volatile("ldmatrix.sync.aligned.m8n8.x4.trans.shared.b16 {%0,%1,%2,%3}, [%4];"
        : "=r"(r[0]), "=r"(r[1]), "=r"(r[2]), "=r"(r[3]) : "r"(a));
}
__device__ __forceinline__ void ldsm2(unsigned* r, const void* p){
    unsigned a = (unsigned)__cvta_generic_to_shared(p);
    asm volatile("ldmatrix.sync.aligned.m8n8.x2.shared.b16 {%0,%1}, [%2];"
        : "=r"(r[0]), "=r"(r[1]) : "r"(a));
}
__device__ __forceinline__ void cpa16(void* dst_smem, const void* src){
    unsigned sa = (unsigned)__cvta_generic_to_shared(dst_smem);
    asm volatile("cp.async.cg.shared.global [%0], [%1], 16;" :: "r"(sa), "l"(src));
}
#define CPA_COMMIT asm volatile("cp.async.commit_group;")
#define CPA_WAIT0  asm volatile("cp.async.wait_group 0;")

// producer publish: all threads fence, then one increments the counter
__device__ __forceinline__ void publish(int* cnt){
    __threadfence();
    __syncthreads();
    if (threadIdx.x == 0) atomicAdd(cnt, 1);
}
// consumer wait: thread 0 spins until counter reaches need
__device__ __forceinline__ void await(int* cnt, int need){
    if (threadIdx.x == 0) {
        while (atomicAdd(cnt, 0) < need) __nanosleep(128);
    }
    __syncthreads();
    __threadfence();
}

// ---------------------------------------------------------------------------
// Mask conversion (dtype auto-detect; bench data treated strictly as data)
// + zero the dependency counters for this call (graph-replay safe).
// ---------------------------------------------------------------------------
__global__ void mask_convert(const unsigned char* __restrict__ raw,
                             float* __restrict__ fmask,
                             int* __restrict__ qcnt, int* __restrict__ tcnt)
{
    __shared__ int s_m1, s_m23, s_gt1;
    int t = threadIdx.x;
    if (t < CB) qcnt[t] = 0;
    if (t < 64) tcnt[t] = 0;
    if (t == 0) { s_m1 = 0; s_m23 = 0; s_gt1 = 0; }
    __syncthreads();
    int m1 = 0, m23 = 0, g = 0;
    for (int i = t; i < MROWS; i += 256) {
        unsigned char v = raw[i];
        if (v) {
            int p = i & 3;
            if (p == 1) m1 = 1;
            if (p >= 2) m23 = 1;
            if (v > 1) g = 1;
        }
    }
    if (m1)  atomicOr(&s_m1, 1);
    if (m23) atomicOr(&s_m23, 1);
    if (g)   atomicOr(&s_gt1, 1);
    __syncthreads();
    int mis = s_m1 | s_m23;
    int mode;
    if (!mis)            mode = 0;
    else if (!s_gt1)     mode = 1;
    else if (s_m1)       mode = 3;
    else                 mode = 2;
    for (int i = t; i < MROWS; i += 256) {
        float f;
        if (mode == 0)      f = (((const int*)raw)[i]            != 0)   ? 1.f : 0.f;
        else if (mode == 1) f = (raw[i]                          != 0)   ? 1.f : 0.f;
        else if (mode == 2) f = (((const float*)raw)[i]          != 0.f) ? 1.f : 0.f;
        else                f = (((const unsigned short*)raw)[i] != 0)   ? 1.f : 0.f;
        fmask[i] = f;
    }
}

// ---------------------------------------------------------------------------
// Fused splitter: x, qkv_w, w1, w2, wr in one launch.
// ---------------------------------------------------------------------------
#define SPL0 (MROWS*CD)
#define SPL1 (QKVLD*CD)
#define SPL2 (CO*CO)
#define SPL3 (CO*CO)
#define SPL4 (CO*CD)
#define SPLT (SPL0+SPL1+SPL2+SPL3+SPL4)
__global__ void split5(
    const float* __restrict__ s0, const float* __restrict__ s1,
    const float* __restrict__ s2, const float* __restrict__ s3,
    const float* __restrict__ s4,
    __nv_bfloat16* __restrict__ h0, __nv_bfloat16* __restrict__ l0,
    __nv_bfloat16* __restrict__ h1, __nv_bfloat16* __restrict__ l1,
    __nv_bfloat16* __restrict__ h2, __nv_bfloat16* __restrict__ l2,
    __nv_bfloat16* __restrict__ h3, __nv_bfloat16* __restrict__ l3,
    __nv_bfloat16* __restrict__ h4, __nv_bfloat16* __restrict__ l4)
{
    int i = blockIdx.x * 256 + threadIdx.x;
    if (i >= SPLT) return;
    const float* s; __nv_bfloat16 *h, *l; int j = i;
    if (j < SPL0)                { s = s0; h = h0; l = l0; }
    else if ((j -= SPL0) < SPL1) { s = s1; h = h1; l = l1; }
    else if ((j -= SPL1) < SPL2) { s = s2; h = h2; l = l2; }
    else if ((j -= SPL2) < SPL3) { s = s3; h = h3; l = l3; }
    else { j -= SPL3;              s = s4; h = h4; l = l4; }
    __nv_bfloat16 hh, ll;
    bsplit(s[j], hh, ll);
    h[j] = hh; l[j] = ll;
}

// ---------------------------------------------------------------------------
// HMMA NT GEMM body (bf16x3), BK=32, cp.async double-buffered, ldmatrix.
// Dynamic smem: Ah[2][2560] | Al | Wh | Wl = 81920 B, row stride 20 u32.
// 128x128 tile, 256 thr (8 warps = 2m x 4n).
// EPI: 0 split-store; 1 relu+split-store; 2 Cf=0.5v; 3 Cf+=0.5*fmask[m]*v
// ---------------------------------------------------------------------------
#define GW 20
#define GSTG (128*GW)
#define GEMM_SMEM (8*GSTG*4)  // 81920

template<int EPI>
__device__ __forceinline__ void gemm_body(
    unsigned* sm, int bx, int by,
    const __nv_bfloat16* __restrict__ Ahg, const __nv_bfloat16* __restrict__ Alg,
    const __nv_bfloat16* __restrict__ Whg, const __nv_bfloat16* __restrict__ Wlg,
    const float* __restrict__ bias, const float* __restrict__ fmask,
    float* __restrict__ Cf, __nv_bfloat16* __restrict__ Ch, __nv_bfloat16* __restrict__ Cl,
    int K, int lda, int ldw, int ldc)
{
    unsigned* Ah = sm;
    unsigned* Al = sm + 2*GSTG;
    unsigned* Wh = sm + 4*GSTG;
    unsigned* Wl = sm + 6*GSTG;
    const int tid = threadIdx.x;
    const int lane = tid & 31, wid = tid >> 5;
    const int wm = wid & 1, wn = wid >> 1;
    const int row0 = by * 128, col0 = bx * 128;
    const int lr = tid >> 1, lq = tid & 1;
    const int qr = lane >> 2, qk = lane & 3;

    const int arow  = wm*64 + (lane & 7) + ((lane >> 3) & 1) * 8;
    const int aword = ((lane >> 4) & 1) * 4;
    const int brow  = wn*32 + (lane & 7);
    const int bword = ((lane >> 3) & 1) * 4;

    float acc[4][4][4];
    #pragma unroll
    for (int mt = 0; mt < 4; mt++)
        #pragma unroll
        for (int nt = 0; nt < 4; nt++)
            #pragma unroll
            for (int i = 0; i < 4; i++) acc[mt][nt][i] = 0.f;

    {
        size_t aoff = (size_t)(row0 + lr) * lda + lq * 16;
        size_t woff = (size_t)(col0 + lr) * ldw + lq * 16;
        #pragma unroll
        for (int j = 0; j < 2; j++) {
            cpa16(&Ah[lr*GW + lq*8 + j*4], Ahg + aoff + j*8);
            cpa16(&Al[lr*GW + lq*8 + j*4], Alg + aoff + j*8);
            cpa16(&Wh[lr*GW + lq*8 + j*4], Whg + woff + j*8);
            cpa16(&Wl[lr*GW + lq*8 + j*4], Wlg + woff + j*8);
        }
    }
    CPA_COMMIT;

    int st = 0;
    for (int k0 = 0; k0 < K; k0 += 32, st ^= 1) {
        CPA_WAIT0;
        __syncthreads();
        if (k0 + 32 < K) {
            const int so = (st^1) * GSTG;
            size_t aoff = (size_t)(row0 + lr) * lda + k0 + 32 + lq * 16;
            size_t woff = (size_t)(col0 + lr) * ldw + k0 + 32 + lq * 16;
            #pragma unroll
            for (int j = 0; j < 2; j++) {
                cpa16(&Ah[so + lr*GW + lq*8 + j*4], Ahg + aoff + j*8);
                cpa16(&Al[so + lr*GW + lq*8 + j*4], Alg + aoff + j*8);
                cpa16(&Wh[so + lr*GW + lq*8 + j*4], Whg + woff + j*8);
                cpa16(&Wl[so + lr*GW + lq*8 + j*4], Wlg + woff + j*8);
            }
        }
        CPA_COMMIT;

        const int sc = st * GSTG;
        #pragma unroll
        for (int g = 0; g < 2; g++) {
            unsigned afh[4][4], afl[4][4], bfh[4][2], bfl[4][2];
            #pragma unroll
            for (int mt = 0; mt < 4; mt++) {
                ldsm4(afh[mt], &Ah[sc + (arow + mt*16)*GW + g*8 + aword]);
                ldsm4(afl[mt], &Al[sc + (arow + mt*16)*GW + g*8 + aword]);
            }
            #pragma unroll
            for (int nt = 0; nt < 4; nt++) {
                ldsm2(bfh[nt], &Wh[sc + (brow + nt*8)*GW + g*8 + bword]);
                ldsm2(bfl[nt], &Wl[sc + (brow + nt*8)*GW + g*8 + bword]);
            }
            #pragma unroll
            for (int mt = 0; mt < 4; mt++)
                #pragma unroll
                for (int nt = 0; nt < 4; nt++) {
                    mma16816(acc[mt][nt], afh[mt], bfh[nt]);
                    mma16816(acc[mt][nt], afh[mt], bfl[nt]);
                    mma16816(acc[mt][nt], afl[mt], bfh[nt]);
                }
        }
    }

    #pragma unroll
    for (int mt = 0; mt < 4; mt++)
        #pragma unroll
        for (int nt = 0; nt < 4; nt++) {
            const float* a = acc[mt][nt];
            int rbase = row0 + wm*64 + mt*16 + qr;
            int cbase = col0 + wn*32 + nt*8 + qk*2;
            float bv0 = bias[cbase], bv1 = bias[cbase + 1];
            #pragma unroll
            for (int hf = 0; hf < 2; hf++) {
                int r = rbase + hf*8;
                float v0 = a[hf*2+0] + bv0;
                float v1 = a[hf*2+1] + bv1;
                size_t idx = (size_t)r * ldc + cbase;
                if constexpr (EPI == 0 || EPI == 1) {
                    if constexpr (EPI == 1) { v0 = fmaxf(v0, 0.f); v1 = fmaxf(v1, 0.f); }
                    unsigned pl, ph = pksplit(v0, v1, pl);
                    *(unsigned*)(Ch + idx) = ph;
                    *(unsigned*)(Cl + idx) = pl;
                } else if constexpr (EPI == 2) {
                    float2 o; o.x = 0.5f*v0; o.y = 0.5f*v1;
                    *(float2*)(Cf + idx) = o;
                } else {
                    float fm = 0.5f * fmask[r];
                    float2 cur = *(float2*)(Cf + idx);
                    cur.x += fm*v0; cur.y += fm*v1;
                    *(float2*)(Cf + idx) = cur;
                }
            }
        }
}

// ---------------------------------------------------------------------------
// Flash body (R13 form: single-buffer K/V, V row-major + ldsm4t, pksplit).
// ---------------------------------------------------------------------------
#define KS_STRIDE 36
#define KS_WORDS (128*KS_STRIDE)
#define FAT_SMEM (GEMM_SMEM)             // 81920 >= flash's 73728

__device__ __forceinline__ void flash_body(
    unsigned* smem, int qt, int b, int h,
    const __nv_bfloat16* __restrict__ qh, const __nv_bfloat16* __restrict__ ql,
    const float* __restrict__ slw, const float* __restrict__ fmask,
    __nv_bfloat16* __restrict__ Hh, __nv_bfloat16* __restrict__ Hl)
{
    unsigned* Ksh = smem;
    unsigned* Ksl = smem + KS_WORDS;
    unsigned* Vsh = smem + 2*KS_WORDS;
    unsigned* Vsl = smem + 3*KS_WORDS;

    const int tid = threadIdx.x;
    const int lane = tid & 31, wid = tid >> 5;
    const int qr = lane >> 2, qk = lane & 3;

    const size_t bhq = (size_t)b*CN*QKVLD + h*CHD;
    const size_t bhk = bhq + CO;
    const size_t bhv = bhq + 2*CO;

    const int lrow = tid >> 1, lq = tid & 1;
    const int krow  = ((lane >> 4) & 1) * 8 + (lane & 7);
    const int kword = ((lane >> 3) & 1) * 4;
    const int vrow  = lane & 15;
    const int vword = (lane >> 4) * 4;

    {
        size_t qoff = bhq + (size_t)(qt*128 + lrow)*QKVLD + lq*32;
        #pragma unroll
        for (int i = 0; i < 4; i++) {
            *(uint4*)&Ksh[lrow*KS_STRIDE + lq*16 + i*4] = *(const uint4*)(qh + qoff + i*8);
            *(uint4*)&Ksl[lrow*KS_STRIDE + lq*16 + i*4] = *(const uint4*)(ql + qoff + i*8);
        }
    }
    __syncthreads();
    unsigned qfh[4][4], qfl[4][4];
    #pragma unroll
    for (int kw = 0; kw < 4; kw++) {
        int r0 = (wid*16 + qr) * KS_STRIDE + kw*8;
        int r8 = (wid*16 + qr + 8) * KS_STRIDE + kw*8;
        qfh[kw][0] = Ksh[r0 + qk];     qfh[kw][1] = Ksh[r8 + qk];
        qfh[kw][2] = Ksh[r0 + qk + 4]; qfh[kw][3] = Ksh[r8 + qk + 4];
        qfl[kw][0] = Ksl[r0 + qk];     qfl[kw][1] = Ksl[r8 + qk];
        qfl[kw][2] = Ksl[r0 + qk + 4]; qfl[kw][3] = Ksl[r8 + qk + 4];
    }
    __syncthreads();

    const float wd = slw[h];
    float o[8][4];
    #pragma unroll
    for (int i = 0; i < 8; i++)
        #pragma unroll
        for (int j = 0; j < 4; j++) o[i][j] = 0.f;
    float m0 = -1e30f, m1 = -1e30f, l0 = 0.f, l1 = 0.f;

    for (int kt = 0; kt < 8; kt++) {
        {
            size_t koff = bhk + (size_t)(kt*128 + lrow)*QKVLD + lq*32;
            size_t voff = bhv + (size_t)(kt*128 + lrow)*QKVLD + lq*32;
            #pragma unroll
            for (int i = 0; i < 4; i++) {
                *(uint4*)&Ksh[lrow*KS_STRIDE + lq*16 + i*4] = *(const uint4*)(qh + koff + i*8);
                *(uint4*)&Ksl[lrow*KS_STRIDE + lq*16 + i*4] = *(const uint4*)(ql + koff + i*8);
                *(uint4*)&Vsh[lrow*KS_STRIDE + lq*16 + i*4] = *(const uint4*)(qh + voff + i*8);
                *(uint4*)&Vsl[lrow*KS_STRIDE + lq*16 + i*4] = *(const uint4*)(ql + voff + i*8);
            }
        }
        __syncthreads();

        const float* fmc = fmask + b*CN + kt*128;

        float s[16][4];
        #pragma unroll
        for (int nt = 0; nt < 16; nt++)
            #pragma unroll
            for (int i = 0; i < 4; i++) s[nt][i] = 0.f;
        #pragma unroll
        for (int ntp = 0; ntp < 8; ntp++) {
            float* sA = s[2*ntp];
            float* sB = s[2*ntp + 1];
            #pragma unroll
            for (int kw = 0; kw < 4; kw++) {
                unsigned kh[4], kl[4];
                ldsm4(kh, &Ksh[(ntp*16 + krow)*KS_STRIDE + kw*8 + kword]);
                ldsm4(kl, &Ksl[(ntp*16 + krow)*KS_STRIDE + kw*8 + kword]);
                mma16816(sA, qfh[kw], kh + 0);
                mma16816(sA, qfh[kw], kl + 0);
                mma16816(sA, qfl[kw], kh + 0);
                mma16816(sB, qfh[kw], kh + 2);
                mma16816(sB, qfh[kw], kl + 2);
                mma16816(sB, qfl[kw], kh + 2);
            }
        }

        const int lr0 = wid*16 + qr, lr1 = lr0 + 8;
        float tmax0 = -3e38f, tmax1 = -3e38f;
        #pragma unroll
        for (int nt = 0; nt < 16; nt++) {
            int c0 = nt*8 + qk*2;
            float2 cmv = *(const float2*)(fmc + c0);
            float v0 = s[nt][0]*0.125f, v1 = s[nt][1]*0.125f;
            float v2 = s[nt][2]*0.125f, v3 = s[nt][3]*0.125f;
            if (qt == kt) {
                if (lr0 == c0)     v0 += wd;
                if (lr0 == c0 + 1) v1 += wd;
                if (lr1 == c0)     v2 += wd;
                if (lr1 == c0 + 1) v3 += wd;
            }
            if (cmv.x == 0.f) { v0 = -1e6f; v2 = -1e6f; }
            if (cmv.y == 0.f) { v1 = -1e6f; v3 = -1e6f; }
            s[nt][0] = v0; s[nt][1] = v1; s[nt][2] = v2; s[nt][3] = v3;
            tmax0 = fmaxf(tmax0, fmaxf(v0, v1));
            tmax1 = fmaxf(tmax1, fmaxf(v2, v3));
        }
        #pragma unroll
        for (int off = 1; off <= 2; off <<= 1) {
            tmax0 = fmaxf(tmax0, __shfl_xor_sync(0xffffffffu, tmax0, off));
            tmax1 = fmaxf(tmax1, __shfl_xor_sync(0xffffffffu, tmax1, off));
        }
        float mn0 = fmaxf(m0, tmax0), mn1 = fmaxf(m1, tmax1);
        float sc0 = __expf(m0 - mn0), sc1 = __expf(m1 - mn1);
        m0 = mn0; m1 = mn1;
        l0 *= sc0; l1 *= sc1;
        #pragma unroll
        for (int nt2 = 0; nt2 < 8; nt2++) {
            o[nt2][0] *= sc0; o[nt2][1] *= sc0;
            o[nt2][2] *= sc1; o[nt2][3] *= sc1;
        }
        float rs0 = 0.f, rs1 = 0.f;
        #pragma unroll
        for (int nt = 0; nt < 16; nt++) {
            float p0 = __expf(s[nt][0] - mn0);
            float p1 = __expf(s[nt][1] - mn0);
            float p2 = __expf(s[nt][2] - mn1);
            float p3 = __expf(s[nt][3] - mn1);
            rs0 += p0 + p1; rs1 += p2 + p3;
            s[nt][0] = p0; s[nt][1] = p1; s[nt][2] = p2; s[nt][3] = p3;
        }
        #pragma unroll
        for (int off = 1; off <= 2; off <<= 1) {
            rs0 += __shfl_xor_sync(0xffffffffu, rs0, off);
            rs1 += __shfl_xor_sync(0xffffffffu, rs1, off);
        }
        l0 += rs0; l1 += rs1;

        #pragma unroll
        for (int kk = 0; kk < 8; kk++) {
            const float* t0 = s[2*kk];
            const float* t1 = s[2*kk + 1];
            unsigned ah[4], al[4];
            ah[0] = pksplit(t0[0], t0[1], al[0]);
            ah[1] = pksplit(t0[2], t0[3], al[1]);
            ah[2] = pksplit(t1[0], t1[1], al[2]);
            ah[3] = pksplit(t1[2], t1[3], al[3]);
            #pragma unroll
            for (int ntp = 0; ntp < 4; ntp++) {
                unsigned vh[4], vl[4];
                ldsm4t(vh, &Vsh[(kk*16 + vrow)*KS_STRIDE + ntp*8 + vword]);
                ldsm4t(vl, &Vsl[(kk*16 + vrow)*KS_STRIDE + ntp*8 + vword]);
                mma16816(o[2*ntp],     ah, vh + 0);
                mma16816(o[2*ntp],     ah, vl + 0);
                mma16816(o[2*ntp],     al, vh + 0);
                mma16816(o[2*ntp + 1], ah, vh + 2);
                mma16816(o[2*ntp + 1], ah, vl + 2);
                mma16816(o[2*ntp + 1], al, vh + 2);
            }
        }
        __syncthreads();
    }

    const int grow0 = b*CN + qt*128 + wid*16 + qr;
    const int grow1 = grow0 + 8;
    float f0 = fmask[grow0] / l0;
    float f1 = fmask[grow1] / l1;
    #pragma unroll
    for (int nt2 = 0; nt2 < 8; nt2++) {
        int col = h*CHD + nt2*8 + qk*2;
        size_t i0 = (size_t)grow0*CO + col;
        size_t i1 = (size_t)grow1*CO + col;
        unsigned pl0, ph0 = pksplit(o[nt2][0]*f0, o[nt2][1]*f0, pl0);
        unsigned pl1, ph1 = pksplit(o[nt2][2]*f1, o[nt2][3]*f1, pl1);
        *(unsigned*)(Hh + i0) = ph0;
        *(unsigned*)(Hl + i0) = pl0;
        *(unsigned*)(Hh + i1) = ph1;
        *(unsigned*)(Hl + i1) = pl1;
    }
}

// ---------------------------------------------------------------------------
// MEGA kernel (1536 blocks): qkv GEMM tiles + flash tiles + residual tiles,
// interleaved per batch with spin-fence dependencies.
// ---------------------------------------------------------------------------
__global__ void __launch_bounds__(256, 1) mega(
    const __nv_bfloat16* __restrict__ xh, const __nv_bfloat16* __restrict__ xl,
    const __nv_bfloat16* __restrict__ qwh, const __nv_bfloat16* __restrict__ qwl,
    const float* __restrict__ qkv_b,
    __nv_bfloat16* __restrict__ qh, __nv_bfloat16* __restrict__ ql,
    const float* __restrict__ slw, const float* __restrict__ fmask,
    __nv_bfloat16* __restrict__ Hh, __nv_bfloat16* __restrict__ Hl,
    const __nv_bfloat16* __restrict__ wrh, const __nv_bfloat16* __restrict__ wrl,
    const float* __restrict__ br, float* __restrict__ out,
    int* __restrict__ qcnt)
{
    extern __shared__ unsigned smem[];
    const int bid = blockIdx.x;

    int kind, batch, sub;   // kind 0=qkv 1=flash 2=residual
    if (bid < 96)            { kind = 0; batch = 0; sub = bid; }
    else if (bid < 1216) {
        int t = bid - 96, g = t / 160, r = t % 160;
        if (r < 96)          { kind = 0; batch = g + 1; sub = r; }
        else                 { kind = 1; batch = g;     sub = r - 96; }
    }
    else if (bid < 1280)     { kind = 1; batch = 7; sub = bid - 1216; }
    else                     { kind = 2; batch = 0; sub = bid - 1280; }

    if (kind == 0) {
        int by = batch * 8 + sub / 12;
        int bx = sub % 12;
        gemm_body<0>(smem, bx, by, xh, xl, qwh, qwl, qkv_b, fmask,
                     (float*)0, qh, ql, CD, CD, CD, QKVLD);
        publish(&qcnt[batch]);
    } else if (kind == 1) {
        await(&qcnt[batch], 96);
        int h = sub >> 3, qt = sub & 7;
        flash_body(smem, qt, batch, h, qh, ql, slw, fmask, Hh, Hl);
    } else {
        gemm_body<2>(smem, sub & 3, sub >> 2, xh, xl, wrh, wrl, br, fmask,
                     out, (__nv_bfloat16*)0, (__nv_bfloat16*)0, CD, CD, CD, CO);
    }
}

// ---------------------------------------------------------------------------
// FFN kernel (512 blocks, 2 CTAs/SM via launch_bounds): FFN1 tiles (0..255)
// publish per-row-block counters; FFN2 tiles (256..511) spin then accumulate.
// ---------------------------------------------------------------------------
__global__ void __launch_bounds__(256, 2) ffn_fused(
    const __nv_bfloat16* __restrict__ Hh, const __nv_bfloat16* __restrict__ Hl,
    const __nv_bfloat16* __restrict__ w1h, const __nv_bfloat16* __restrict__ w1l,
    const float* __restrict__ b1,
    __nv_bfloat16* __restrict__ Th, __nv_bfloat16* __restrict__ Tl,
    const __nv_bfloat16* __restrict__ w2h, const __nv_bfloat16* __restrict__ w2l,
    const float* __restrict__ b2,
    const float* __restrict__ fmask, float* __restrict__ out,
    int* __restrict__ tcnt)
{
    extern __shared__ unsigned smem[];
    const int bid = blockIdx.x;
    if (bid < 256) {
        int by = bid >> 2, bx = bid & 3;
        gemm_body<1>(smem, bx, by, Hh, Hl, w1h, w1l, b1, fmask,
                     (float*)0, Th, Tl, CO, CO, CO, CO);
        publish(&tcnt[by]);
    } else {
        int j = bid - 256;
        int by = j >> 2, bx = j & 3;
        await(&tcnt[by], 4);
        gemm_body<3>(smem, bx, by, Th, Tl, w2h, w2l, b2, fmask,
                     out, (__nv_bfloat16*)0, (__nv_bfloat16*)0, CO, CO, CO, CO);
    }
}

// ---------------------------------------------------------------------------
extern "C" void kernel_launch(void* const* d_in, const int* in_sizes, int n_in,
                              void* d_out, int out_size)
{
    const float* x = 0;  const unsigned char* mask_raw = 0;
    const float* slw = 0; const float* qkv_w = 0; const float* qkv_b = 0;
    const float* wbig[3] = {0,0,0}; const float* bsm[3] = {0,0,0};
    int nw = 0, nb = 0;

    for (int i = 0; i < n_in; i++) {
        switch (in_sizes[i]) {
            case 4194304: x        = (const float*)d_in[i]; break;
            case 8388608: /* adj unused */                  break;
            case 8192:    mask_raw = (const unsigned char*)d_in[i]; break;
            case 8:       slw      = (const float*)d_in[i]; break;
            case 786432:  qkv_w    = (const float*)d_in[i]; break;
            case 1536:    qkv_b    = (const float*)d_in[i]; break;
            case 262144:  if (nw < 3) wbig[nw++] = (const float*)d_in[i]; break;
            case 512:     if (nb < 3) bsm[nb++]  = (const float*)d_in[i]; break;
            default: break;
        }
    }
    const float *w1 = wbig[0], *w2 = wbig[1], *wr = wbig[2];
    const float *b1 = bsm[0],  *b2 = bsm[1],  *br = bsm[2];
    float* out = (float*)d_out;

    void *pf, *pqc, *ptc, *pxh, *pxl, *pqwh, *pqwl, *pw1h, *pw1l, *pw2h, *pw2l;
    void *pwrh, *pwrl, *pqh, *pql, *pHh, *pHl, *pTh, *pTl;
    cudaGetSymbolAddress(&pf,   g_fmask);
    cudaGetSymbolAddress(&pqc,  g_qcnt);
    cudaGetSymbolAddress(&ptc,  g_tcnt);
    cudaGetSymbolAddress(&pxh,  g_xh);   cudaGetSymbolAddress(&pxl,  g_xl);
    cudaGetSymbolAddress(&pqwh, g_qwh);  cudaGetSymbolAddress(&pqwl, g_qwl);
    cudaGetSymbolAddress(&pw1h, g_w1h);  cudaGetSymbolAddress(&pw1l, g_w1l);
    cudaGetSymbolAddress(&pw2h, g_w2h);  cudaGetSymbolAddress(&pw2l, g_w2l);
    cudaGetSymbolAddress(&pwrh, g_wrh);  cudaGetSymbolAddress(&pwrl, g_wrl);
    cudaGetSymbolAddress(&pqh,  g_qh);   cudaGetSymbolAddress(&pql,  g_ql);
    cudaGetSymbolAddress(&pHh,  g_Hh);   cudaGetSymbolAddress(&pHl,  g_Hl);
    cudaGetSymbolAddress(&pTh,  g_Th);   cudaGetSymbolAddress(&pTl,  g_Tl);

    float* fmp = (float*)pf;
    int *qcnt = (int*)pqc, *tcnt = (int*)ptc;
    __nv_bfloat16 *xh=(__nv_bfloat16*)pxh, *xl=(__nv_bfloat16*)pxl;
    __nv_bfloat16 *qwh=(__nv_bfloat16*)pqwh, *qwl=(__nv_bfloat16*)pqwl;
    __nv_bfloat16 *w1h=(__nv_bfloat16*)pw1h, *w1l=(__nv_bfloat16*)pw1l;
    __nv_bfloat16 *w2h=(__nv_bfloat16*)pw2h, *w2l=(__nv_bfloat16*)pw2l;
    __nv_bfloat16 *wrh=(__nv_bfloat16*)pwrh, *wrl=(__nv_bfloat16*)pwrl;
    __nv_bfloat16 *qhp=(__nv_bfloat16*)pqh, *qlp=(__nv_bfloat16*)pql;
    __nv_bfloat16 *Hhp=(__nv_bfloat16*)pHh, *Hlp=(__nv_bfloat16*)pHl;
    __nv_bfloat16 *Thp=(__nv_bfloat16*)pTh, *Tlp=(__nv_bfloat16*)pTl;

    static int smem_set = 0;
    if (!smem_set) {
        cudaFuncSetAttribute(mega, cudaFuncAttributeMaxDynamicSharedMemorySize,
                             FAT_SMEM);
        cudaFuncSetAttribute(ffn_fused, cudaFuncAttributeMaxDynamicSharedMemorySize,
                             GEMM_SMEM);
        smem_set = 1;
    }

    // 0) mask convert + counter reset, fused one-time splits
    mask_convert<<<1, 256>>>(mask_raw, fmp, qcnt, tcnt);
    split5<<<(SPLT+255)/256, 256>>>(x, qkv_w, w1, w2, wr,
                                    xh, xl, qwh, qwl, w1h, w1l, w2h, w2l, wrh, wrl);

    // 1) qkv + flash + residual in ONE launch (spin-fenced pipelining)
    mega<<<1536, 256, FAT_SMEM>>>(xh, xl, qwh, qwl, qkv_b, qhp, qlp,
                                  slw, fmp, Hhp, Hlp, wrh, wrl, br, out, qcnt);

    // 2) FFN1 + FFN2 in ONE launch (spin-fenced, 2 CTAs/SM)
    ffn_fused<<<512, 256, GEMM_SMEM>>>(Hhp, Hlp, w1h, w1l, b1, Thp, Tlp,
                                       w2h, w2l, b2, fmp, out, tcnt);
}